// round 2
// baseline (speedup 1.0000x reference)
#include <cuda_runtime.h>
#include <cuda_bf16.h>
#include <cstdint>

// Problem constants (fixed by the reference)
#define NNODES 50000
#define NEDGES 400000
#define CH     256          // output channels of both layers
#define K1     512          // layer-1 inner dim
#define K2     256          // layer-2 inner dim

// ---------------------------------------------------------------------------
// Scratch (no allocations allowed -> __device__ globals, referenced directly
// from device code; no cudaGetSymbolAddress anywhere)
// ---------------------------------------------------------------------------
__device__ float g_h1[(size_t)NNODES * CH];     // GEMM1 output
__device__ float g_hr[(size_t)NNODES * CH];     // layer-1 aggregated + relu
__device__ float g_h2[(size_t)NNODES * CH];     // GEMM2 output
__device__ float g_dinv[NNODES];
__device__ float g_deg[NNODES];
__device__ int   g_is64;                        // edge_index dtype flag

// ---------------------------------------------------------------------------
// edge_index dtype detection: reference requests int64, but JAX without x64
// silently emits int32. Values are uniform in [0, NNODES); reading an int32
// buffer as int64 yields values >= 2^32 almost surely within 256 samples.
// ---------------------------------------------------------------------------
__global__ void k_detect(const long long* __restrict__ ei) {
    if (blockIdx.x == 0 && threadIdx.x == 0) {
        int is64 = 1;
        for (int i = 0; i < 256; i++) {
            long long v = ei[i];
            if (v < 0 || v >= NNODES) { is64 = 0; break; }
        }
        g_is64 = is64;
    }
}

__device__ __forceinline__ int edge_idx(const void* ei, int half, int e) {
    if (g_is64) return (int)((const long long*)ei)[(size_t)half * NEDGES + e];
    return ((const int*)ei)[(size_t)half * NEDGES + e];
}

// ---------------------------------------------------------------------------
// Degree / dinv
// ---------------------------------------------------------------------------
__global__ void k_init_deg() {
    int i = blockIdx.x * blockDim.x + threadIdx.x;
    if (i < NNODES) g_deg[i] = 1.0f;            // self loop
}

__global__ void k_add_deg(const void* __restrict__ ei) {
    int e = blockIdx.x * blockDim.x + threadIdx.x;
    if (e < NEDGES) atomicAdd(&g_deg[edge_idx(ei, 1, e)], 1.0f);
}

__global__ void k_dinv() {
    int i = blockIdx.x * blockDim.x + threadIdx.x;
    if (i < NNODES) g_dinv[i] = rsqrtf(g_deg[i]);
}

// ---------------------------------------------------------------------------
// SGEMM: C[M, 256] = A[M, K] * B[256, K]^T   (both K-contiguous, row-major)
// Tiles: BM=128, BN=64, BK=16; thread tile 8x4; 256 threads.
// ---------------------------------------------------------------------------
#define BM 128
#define BN 64
#define BK 16
#define TM 8
#define TN 4

__device__ __forceinline__ void sgemm_body(
    const float* __restrict__ A, const float* __restrict__ B,
    float* __restrict__ C, int M, int K)
{
    __shared__ float As[BK][BM + 4];
    __shared__ float Bs[BK][BN + 4];

    const int t    = threadIdx.x;
    const int brow = blockIdx.x * BM;
    const int bcol = blockIdx.y * BN;
    const int ty   = t / 16;     // 0..15 -> row group (8 rows each)
    const int tx   = t % 16;     // 0..15 -> col group (4 cols each)

    float acc[TM][TN];
#pragma unroll
    for (int i = 0; i < TM; i++)
#pragma unroll
        for (int j = 0; j < TN; j++) acc[i][j] = 0.0f;

    for (int k0 = 0; k0 < K; k0 += BK) {
        // Load A tile: 128 rows x 16 cols = 512 float4, 2 per thread
#pragma unroll
        for (int it = 0; it < 2; it++) {
            int idx = t + it * 256;
            int r   = idx >> 2;          // 0..127
            int cv  = idx & 3;           // float4 index within 16 cols
            float4 v = make_float4(0.f, 0.f, 0.f, 0.f);
            int gr = brow + r;
            if (gr < M)
                v = *(const float4*)&A[(size_t)gr * K + k0 + cv * 4];
            As[cv * 4 + 0][r] = v.x;
            As[cv * 4 + 1][r] = v.y;
            As[cv * 4 + 2][r] = v.z;
            As[cv * 4 + 3][r] = v.w;
        }
        // Load B tile: 64 rows x 16 cols = 256 float4, 1 per thread
        {
            int r  = t >> 2;             // 0..63
            int cv = t & 3;
            float4 v = *(const float4*)&B[(size_t)(bcol + r) * K + k0 + cv * 4];
            Bs[cv * 4 + 0][r] = v.x;
            Bs[cv * 4 + 1][r] = v.y;
            Bs[cv * 4 + 2][r] = v.z;
            Bs[cv * 4 + 3][r] = v.w;
        }
        __syncthreads();

#pragma unroll
        for (int kk = 0; kk < BK; kk++) {
            float a[TM], b[TN];
#pragma unroll
            for (int i = 0; i < TM; i++) a[i] = As[kk][ty * TM + i];
#pragma unroll
            for (int j = 0; j < TN; j++) b[j] = Bs[kk][tx * TN + j];
#pragma unroll
            for (int i = 0; i < TM; i++)
#pragma unroll
                for (int j = 0; j < TN; j++)
                    acc[i][j] = fmaf(a[i], b[j], acc[i][j]);
        }
        __syncthreads();
    }

    // Epilogue: write 8 rows x 1 float4 each
#pragma unroll
    for (int i = 0; i < TM; i++) {
        int gr = brow + ty * TM + i;
        if (gr < M) {
            float4 v = make_float4(acc[i][0], acc[i][1], acc[i][2], acc[i][3]);
            *(float4*)&C[(size_t)gr * CH + bcol + tx * TN] = v;
        }
    }
}

__global__ void __launch_bounds__(256, 2)
k_sgemm1(const float* __restrict__ x, const float* __restrict__ W1) {
    sgemm_body(x, W1, g_h1, NNODES, K1);
}

__global__ void __launch_bounds__(256, 2)
k_sgemm2(const float* __restrict__ W2) {
    sgemm_body(g_hr, W2, g_h2, NNODES, K2);
}

// ---------------------------------------------------------------------------
// Aggregation
// ---------------------------------------------------------------------------

// out[i,:] = h[i,:] * dinv[i]^2 (+ bias)   -- self-loop term, full overwrite
__device__ __forceinline__ void self_init_body(
    const float* __restrict__ h, const float* __restrict__ bias,
    float* __restrict__ out)
{
    int tid = blockIdx.x * blockDim.x + threadIdx.x;   // NNODES * 64 threads
    if (tid >= NNODES * (CH / 4)) return;
    int node = tid >> 6;           // /64
    int c4   = tid & 63;
    float s = g_dinv[node];
    s *= s;
    float4 v = *(const float4*)&h[(size_t)node * CH + c4 * 4];
    float4 r;
    if (bias) {
        const float4 b = *(const float4*)&bias[c4 * 4];
        r = make_float4(fmaf(v.x, s, b.x), fmaf(v.y, s, b.y),
                        fmaf(v.z, s, b.z), fmaf(v.w, s, b.w));
    } else {
        r = make_float4(v.x * s, v.y * s, v.z * s, v.w * s);
    }
    *(float4*)&out[(size_t)node * CH + c4 * 4] = r;
}

__global__ void k_self_init1() { self_init_body(g_h1, nullptr, g_hr); }
__global__ void k_self_init2(const float* __restrict__ b2, float* __restrict__ out) {
    self_init_body(g_h2, b2, out);
}

// For each edge: out[dst,:] += h[src,:] * dinv[src]*dinv[dst]
// 64 lanes per edge; plain atomicAdd (RED.E.ADD.F32), 4 per lane.
__device__ __forceinline__ void edge_scatter_body(
    const void* __restrict__ ei, const float* __restrict__ h,
    float* __restrict__ out)
{
    long long gid = (long long)blockIdx.x * blockDim.x + threadIdx.x;
    int e    = (int)(gid >> 6);
    int lane = (int)(gid & 63);
    if (e >= NEDGES) return;
    int s = edge_idx(ei, 0, e);
    int d = edge_idx(ei, 1, e);
    float w = g_dinv[s] * g_dinv[d];
    float4 v = *(const float4*)&h[(size_t)s * CH + lane * 4];
    float* addr = &out[(size_t)d * CH + lane * 4];
    atomicAdd(addr + 0, v.x * w);
    atomicAdd(addr + 1, v.y * w);
    atomicAdd(addr + 2, v.z * w);
    atomicAdd(addr + 3, v.w * w);
}

__global__ void k_edge_scatter1(const void* __restrict__ ei) {
    edge_scatter_body(ei, g_h1, g_hr);
}
__global__ void k_edge_scatter2(const void* __restrict__ ei, float* __restrict__ out) {
    edge_scatter_body(ei, g_h2, out);
}

// g_hr = relu(g_hr + b1)
__global__ void k_bias_relu(const float* __restrict__ bias)
{
    int tid = blockIdx.x * blockDim.x + threadIdx.x;
    if (tid >= NNODES * (CH / 4)) return;
    int c4 = tid & 63;
    float4 v = *(float4*)&g_hr[(size_t)tid * 4];
    const float4 b = *(const float4*)&bias[c4 * 4];
    v.x = fmaxf(v.x + b.x, 0.f);
    v.y = fmaxf(v.y + b.y, 0.f);
    v.z = fmaxf(v.z + b.z, 0.f);
    v.w = fmaxf(v.w + b.w, 0.f);
    *(float4*)&g_hr[(size_t)tid * 4] = v;
}

// ---------------------------------------------------------------------------
// Launch
// ---------------------------------------------------------------------------
extern "C" void kernel_launch(void* const* d_in, const int* in_sizes, int n_in,
                              void* d_out, int out_size)
{
    const float* x   = (const float*)d_in[0];
    const void*  ei  = d_in[1];                  // int64 or int32 [2, E]
    const float* W1  = (const float*)d_in[2];
    // d_in[3] = b1, d_in[4] = W2, d_in[5] = b2
    const float* b1  = (const float*)d_in[3];
    const float* W2  = (const float*)d_in[4];
    const float* b2  = (const float*)d_in[5];
    float*       out = (float*)d_out;

    const int NTH = 256;
    const int nblk_nodes = (NNODES + NTH - 1) / NTH;
    const int nblk_edges = (NEDGES + NTH - 1) / NTH;
    const int nblk_nc4   = (NNODES * (CH / 4) + NTH - 1) / NTH;
    const long long scat_threads = (long long)NEDGES * 64;
    const int nblk_scat  = (int)((scat_threads + NTH - 1) / NTH);

    dim3 g1((NNODES + BM - 1) / BM, CH / BN);   // (391, 4)

    // dtype detection + degree + dinv
    k_detect<<<1, 32>>>((const long long*)ei);
    k_init_deg<<<nblk_nodes, NTH>>>();
    k_add_deg<<<nblk_edges, NTH>>>(ei);
    k_dinv<<<nblk_nodes, NTH>>>();

    // layer 1
    k_sgemm1<<<g1, NTH>>>(x, W1);
    k_self_init1<<<nblk_nc4, NTH>>>();
    k_edge_scatter1<<<nblk_scat, NTH>>>(ei);
    k_bias_relu<<<nblk_nc4, NTH>>>(b1);

    // layer 2
    k_sgemm2<<<g1, NTH>>>(W2);
    k_self_init2<<<nblk_nc4, NTH>>>(b2, out);
    k_edge_scatter2<<<nblk_scat, NTH>>>(ei, out);
}

// round 5
// speedup vs baseline: 1.1981x; 1.1981x over previous
#include <cuda_runtime.h>
#include <cuda_bf16.h>
#include <cstdint>

// Problem constants (fixed by the reference)
#define NNODES 50000
#define NEDGES 400000
#define CH     256
#define K1     512
#define K2     256

// ---------------------------------------------------------------------------
// Scratch (__device__ globals; no allocations)
// ---------------------------------------------------------------------------
__device__ float g_h1[(size_t)NNODES * CH];
__device__ float g_hr[(size_t)NNODES * CH];
__device__ float g_h2[(size_t)NNODES * CH];
__device__ float g_dinv[NNODES];
__device__ float g_deg[NNODES];
__device__ int   g_is64;

// ---------------------------------------------------------------------------
// Helpers
// ---------------------------------------------------------------------------
__device__ __forceinline__ uint32_t smem_u32(const void* p) {
    uint32_t a;
    asm("{ .reg .u64 t; cvta.to.shared.u64 t, %1; cvt.u32.u64 %0, t; }" : "=r"(a) : "l"(p));
    return a;
}

#define SW128(o) ((o) ^ (((o) >> 3) & 0x70))

__device__ __forceinline__ void ldsm4(uint32_t* r, uint32_t addr) {
    asm volatile("ldmatrix.sync.aligned.m8n8.x4.shared.b16 {%0,%1,%2,%3}, [%4];"
                 : "=r"(r[0]), "=r"(r[1]), "=r"(r[2]), "=r"(r[3]) : "r"(addr));
}

__device__ __forceinline__ void mma16816(float* c, const uint32_t* a,
                                         uint32_t b0, uint32_t b1) {
    asm volatile(
        "mma.sync.aligned.m16n8k16.row.col.f32.bf16.bf16.f32 "
        "{%0,%1,%2,%3}, {%4,%5,%6,%7}, {%8,%9}, {%0,%1,%2,%3};"
        : "+f"(c[0]), "+f"(c[1]), "+f"(c[2]), "+f"(c[3])
        : "r"(a[0]), "r"(a[1]), "r"(a[2]), "r"(a[3]), "r"(b0), "r"(b1));
}

#define STS128W(addr, w0, w1, w2, w3) \
    asm volatile("st.shared.v4.b32 [%0], {%1,%2,%3,%4};" \
                 :: "r"(addr), "r"(w0), "r"(w1), "r"(w2), "r"(w3) : "memory")

// Split two fp32 into bf16x2 hi-word + residual bf16x2 lo-word
__device__ __forceinline__ void bsplit2(float x0, float x1, uint32_t& hi, uint32_t& lo) {
    __nv_bfloat16 h0 = __float2bfloat16_rn(x0);
    __nv_bfloat16 h1 = __float2bfloat16_rn(x1);
    float r0 = x0 - __bfloat162float(h0);
    float r1 = x1 - __bfloat162float(h1);
    __nv_bfloat162 hp, lp;
    hp.x = h0; hp.y = h1;
    lp.x = __float2bfloat16_rn(r0); lp.y = __float2bfloat16_rn(r1);
    hi = *reinterpret_cast<uint32_t*>(&hp);
    lo = *reinterpret_cast<uint32_t*>(&lp);
}

// ---------------------------------------------------------------------------
// bf16 split-3 GEMM: C[M,256] = A[M,K] @ B[256,K]^T, fp32 in/out.
// CTA tile 128x128, BK=64, 256 threads (8 warps, 4m x 2n, warp tile 32x64).
// smem: aHi | aLo | bHi | bLo, each 128 rows x 128B (SW128 swizzle) = 64KB.
// ---------------------------------------------------------------------------
#define GEMM_SMEM (64 * 1024)

__device__ __forceinline__ void mma_gemm_body(
    const float* __restrict__ A, const float* __restrict__ Bw,
    float* __restrict__ C, int M, int K)
{
    extern __shared__ char dsm_raw[];
    const uint32_t base = smem_u32(dsm_raw);
    const uint32_t aHi = base;
    const uint32_t aLo = base + 16384;
    const uint32_t bHi = base + 32768;
    const uint32_t bLo = base + 49152;

    const int t    = threadIdx.x;
    const int wid  = t >> 5;
    const int lane = t & 31;
    const int brow = blockIdx.x * 128;
    const int bcol = blockIdx.y * 128;

    const int warp_m = (wid >> 1) * 32;   // 0,32,64,96
    const int warp_n = (wid & 1) * 64;    // 0,64

    float acc[2][8][4];
#pragma unroll
    for (int i = 0; i < 2; i++)
#pragma unroll
        for (int j = 0; j < 8; j++)
#pragma unroll
            for (int q = 0; q < 4; q++) acc[i][j][q] = 0.0f;

    // ldmatrix per-lane addressing components
    const int lr  = lane & 15;       // row within 16-row fragment
    const int kh  = lane >> 4;       // k-half (0/1)

    const int nch = K >> 6;
    for (int c = 0; c < nch; c++) {
        const int k0 = c << 6;

        // ---- global -> smem (convert to bf16 hi/lo), SW128-swizzled
        // A tile: 128 rows x 64 k. Item = 8 consecutive floats.
        // 128 rows * 8 items = 1024 items -> r = g>>3 (0..127), j = g&7 (0..7)
#pragma unroll
        for (int it = 0; it < 4; it++) {
            int g = t + it * 256;              // 0..1023
            int r = g >> 3, j = g & 7;
            int gr = brow + r;
            float4 v0 = make_float4(0.f, 0.f, 0.f, 0.f), v1 = v0;
            if (gr < M) {
                const float* p = A + (size_t)gr * K + k0 + j * 8;
                v0 = *(const float4*)p;
                v1 = *(const float4*)(p + 4);
            }
            uint32_t h0, l0, h1, l1, h2, l2, h3, l3;
            bsplit2(v0.x, v0.y, h0, l0);  bsplit2(v0.z, v0.w, h1, l1);
            bsplit2(v1.x, v1.y, h2, l2);  bsplit2(v1.z, v1.w, h3, l3);
            uint32_t off = SW128((uint32_t)(r * 128 + j * 16));
            STS128W(aHi + off, h0, h1, h2, h3);
            STS128W(aLo + off, l0, l1, l2, l3);
        }
        // B tile: 128 rows (bcol..bcol+127) x 64 k
#pragma unroll
        for (int it = 0; it < 4; it++) {
            int g = t + it * 256;
            int r = g >> 3, j = g & 7;
            const float* p = Bw + (size_t)(bcol + r) * K + k0 + j * 8;
            float4 v0 = *(const float4*)p;
            float4 v1 = *(const float4*)(p + 4);
            uint32_t h0, l0, h1, l1, h2, l2, h3, l3;
            bsplit2(v0.x, v0.y, h0, l0);  bsplit2(v0.z, v0.w, h1, l1);
            bsplit2(v1.x, v1.y, h2, l2);  bsplit2(v1.z, v1.w, h3, l3);
            uint32_t off = SW128((uint32_t)(r * 128 + j * 16));
            STS128W(bHi + off, h0, h1, h2, h3);
            STS128W(bLo + off, l0, l1, l2, l3);
        }
        __syncthreads();

        // ---- 4 K-steps of 16 within the 64-chunk
#pragma unroll
        for (int s = 0; s < 4; s++) {
            const int jg = s * 2 + kh;    // 16B group index for this lane

            uint32_t ah[2][4], bh[4][4];
#pragma unroll
            for (int mi = 0; mi < 2; mi++) {
                int r = warp_m + mi * 16 + lr;
                ldsm4(ah[mi], aHi + (uint32_t)(r * 128 + ((jg ^ (r & 7)) << 4)));
            }
#pragma unroll
            for (int nj = 0; nj < 4; nj++) {
                int r = warp_n + nj * 16 + lr;
                ldsm4(bh[nj], bHi + (uint32_t)(r * 128 + ((jg ^ (r & 7)) << 4)));
            }
            // hi * hi
#pragma unroll
            for (int mi = 0; mi < 2; mi++)
#pragma unroll
                for (int nj = 0; nj < 4; nj++) {
                    mma16816(acc[mi][nj * 2 + 0], ah[mi], bh[nj][0], bh[nj][2]);
                    mma16816(acc[mi][nj * 2 + 1], ah[mi], bh[nj][1], bh[nj][3]);
                }
            // lo * hi
            {
                uint32_t al[2][4];
#pragma unroll
                for (int mi = 0; mi < 2; mi++) {
                    int r = warp_m + mi * 16 + lr;
                    ldsm4(al[mi], aLo + (uint32_t)(r * 128 + ((jg ^ (r & 7)) << 4)));
                }
#pragma unroll
                for (int mi = 0; mi < 2; mi++)
#pragma unroll
                    for (int nj = 0; nj < 4; nj++) {
                        mma16816(acc[mi][nj * 2 + 0], al[mi], bh[nj][0], bh[nj][2]);
                        mma16816(acc[mi][nj * 2 + 1], al[mi], bh[nj][1], bh[nj][3]);
                    }
            }
            // hi * lo
            {
                uint32_t bl[4][4];
#pragma unroll
                for (int nj = 0; nj < 4; nj++) {
                    int r = warp_n + nj * 16 + lr;
                    ldsm4(bl[nj], bLo + (uint32_t)(r * 128 + ((jg ^ (r & 7)) << 4)));
                }
#pragma unroll
                for (int mi = 0; mi < 2; mi++)
#pragma unroll
                    for (int nj = 0; nj < 4; nj++) {
                        mma16816(acc[mi][nj * 2 + 0], ah[mi], bl[nj][0], bl[nj][2]);
                        mma16816(acc[mi][nj * 2 + 1], ah[mi], bl[nj][1], bl[nj][3]);
                    }
            }
        }
        __syncthreads();
    }

    // ---- epilogue: fragment -> C
    const int qr = lane >> 2;          // 0..7
    const int qc = (lane & 3) * 2;     // 0,2,4,6
#pragma unroll
    for (int mi = 0; mi < 2; mi++) {
        int r0 = brow + warp_m + mi * 16 + qr;
#pragma unroll
        for (int n8 = 0; n8 < 8; n8++) {
            int col = bcol + warp_n + n8 * 8 + qc;
            if (r0 < M) {
                float2 v = make_float2(acc[mi][n8][0], acc[mi][n8][1]);
                *(float2*)&C[(size_t)r0 * 256 + col] = v;
            }
            if (r0 + 8 < M) {
                float2 v = make_float2(acc[mi][n8][2], acc[mi][n8][3]);
                *(float2*)&C[(size_t)(r0 + 8) * 256 + col] = v;
            }
        }
    }
}

__global__ void __launch_bounds__(256)
k_mmagemm1(const float* __restrict__ x, const float* __restrict__ W1) {
    mma_gemm_body(x, W1, g_h1, NNODES, K1);
}
__global__ void __launch_bounds__(256)
k_mmagemm2(const float* __restrict__ W2) {
    mma_gemm_body(g_hr, W2, g_h2, NNODES, K2);
}

// ---------------------------------------------------------------------------
// edge_index dtype detection (int64 per spec; tolerate int32)
// ---------------------------------------------------------------------------
__global__ void k_detect(const long long* __restrict__ ei) {
    if (blockIdx.x == 0 && threadIdx.x == 0) {
        int is64 = 1;
        for (int i = 0; i < 256; i++) {
            long long v = ei[i];
            if (v < 0 || v >= NNODES) { is64 = 0; break; }
        }
        g_is64 = is64;
    }
}

__device__ __forceinline__ int edge_idx(const void* ei, int half, int e) {
    if (g_is64) return (int)((const long long*)ei)[(size_t)half * NEDGES + e];
    return ((const int*)ei)[(size_t)half * NEDGES + e];
}

// ---------------------------------------------------------------------------
// Degree / dinv
// ---------------------------------------------------------------------------
__global__ void k_init_deg() {
    int i = blockIdx.x * blockDim.x + threadIdx.x;
    if (i < NNODES) g_deg[i] = 1.0f;
}
__global__ void k_add_deg(const void* __restrict__ ei) {
    int e = blockIdx.x * blockDim.x + threadIdx.x;
    if (e < NEDGES) atomicAdd(&g_deg[edge_idx(ei, 1, e)], 1.0f);
}
__global__ void k_dinv() {
    int i = blockIdx.x * blockDim.x + threadIdx.x;
    if (i < NNODES) g_dinv[i] = rsqrtf(g_deg[i]);
}

// ---------------------------------------------------------------------------
// Aggregation
// ---------------------------------------------------------------------------
__device__ __forceinline__ void self_init_body(
    const float* __restrict__ h, const float* __restrict__ bias,
    float* __restrict__ out)
{
    int tid = blockIdx.x * blockDim.x + threadIdx.x;
    if (tid >= NNODES * (CH / 4)) return;
    int node = tid >> 6;
    int c4   = tid & 63;
    float s = g_dinv[node];
    s *= s;
    float4 v = *(const float4*)&h[(size_t)node * CH + c4 * 4];
    float4 r;
    if (bias) {
        const float4 b = *(const float4*)&bias[c4 * 4];
        r = make_float4(fmaf(v.x, s, b.x), fmaf(v.y, s, b.y),
                        fmaf(v.z, s, b.z), fmaf(v.w, s, b.w));
    } else {
        r = make_float4(v.x * s, v.y * s, v.z * s, v.w * s);
    }
    *(float4*)&out[(size_t)node * CH + c4 * 4] = r;
}
__global__ void k_self_init1() { self_init_body(g_h1, nullptr, g_hr); }
__global__ void k_self_init2(const float* __restrict__ b2, float* __restrict__ out) {
    self_init_body(g_h2, b2, out);
}

__device__ __forceinline__ void edge_scatter_body(
    const void* __restrict__ ei, const float* __restrict__ h,
    float* __restrict__ out)
{
    long long gid = (long long)blockIdx.x * blockDim.x + threadIdx.x;
    int e    = (int)(gid >> 6);
    int lane = (int)(gid & 63);
    if (e >= NEDGES) return;
    int s = edge_idx(ei, 0, e);
    int d = edge_idx(ei, 1, e);
    float w = g_dinv[s] * g_dinv[d];
    float4 v = *(const float4*)&h[(size_t)s * CH + lane * 4];
    float* addr = &out[(size_t)d * CH + lane * 4];
    atomicAdd(addr + 0, v.x * w);
    atomicAdd(addr + 1, v.y * w);
    atomicAdd(addr + 2, v.z * w);
    atomicAdd(addr + 3, v.w * w);
}
__global__ void k_edge_scatter1(const void* __restrict__ ei) {
    edge_scatter_body(ei, g_h1, g_hr);
}
__global__ void k_edge_scatter2(const void* __restrict__ ei, float* __restrict__ out) {
    edge_scatter_body(ei, g_h2, out);
}

__global__ void k_bias_relu(const float* __restrict__ bias)
{
    int tid = blockIdx.x * blockDim.x + threadIdx.x;
    if (tid >= NNODES * (CH / 4)) return;
    int c4 = tid & 63;
    float4 v = *(float4*)&g_hr[(size_t)tid * 4];
    const float4 b = *(const float4*)&bias[c4 * 4];
    v.x = fmaxf(v.x + b.x, 0.f);
    v.y = fmaxf(v.y + b.y, 0.f);
    v.z = fmaxf(v.z + b.z, 0.f);
    v.w = fmaxf(v.w + b.w, 0.f);
    *(float4*)&g_hr[(size_t)tid * 4] = v;
}

// ---------------------------------------------------------------------------
// Launch
// ---------------------------------------------------------------------------
extern "C" void kernel_launch(void* const* d_in, const int* in_sizes, int n_in,
                              void* d_out, int out_size)
{
    const float* x   = (const float*)d_in[0];
    const void*  ei  = d_in[1];
    const float* W1  = (const float*)d_in[2];
    const float* b1  = (const float*)d_in[3];
    const float* W2  = (const float*)d_in[4];
    const float* b2  = (const float*)d_in[5];
    float*       out = (float*)d_out;

    static bool attr_done = false;
    if (!attr_done) {
        cudaFuncSetAttribute(k_mmagemm1, cudaFuncAttributeMaxDynamicSharedMemorySize, GEMM_SMEM);
        cudaFuncSetAttribute(k_mmagemm2, cudaFuncAttributeMaxDynamicSharedMemorySize, GEMM_SMEM);
        attr_done = true;
    }

    const int NTH = 256;
    const int nblk_nodes = (NNODES + NTH - 1) / NTH;
    const int nblk_edges = (NEDGES + NTH - 1) / NTH;
    const int nblk_nc4   = (NNODES * (CH / 4) + NTH - 1) / NTH;
    const long long scat_threads = (long long)NEDGES * 64;
    const int nblk_scat  = (int)((scat_threads + NTH - 1) / NTH);

    dim3 gg((NNODES + 127) / 128, 2);   // (391, 2)

    // dtype detection + degree + dinv
    k_detect<<<1, 32>>>((const long long*)ei);
    k_init_deg<<<nblk_nodes, NTH>>>();
    k_add_deg<<<nblk_edges, NTH>>>(ei);
    k_dinv<<<nblk_nodes, NTH>>>();

    // layer 1
    k_mmagemm1<<<gg, NTH, GEMM_SMEM>>>(x, W1);
    k_self_init1<<<nblk_nc4, NTH>>>();
    k_edge_scatter1<<<nblk_scat, NTH>>>(ei);
    k_bias_relu<<<nblk_nc4, NTH>>>(b1);

    // layer 2
    k_mmagemm2<<<gg, NTH, GEMM_SMEM>>>(W2);
    k_self_init2<<<nblk_nc4, NTH>>>(b2, out);
    k_edge_scatter2<<<nblk_scat, NTH>>>(ei, out);
}

// round 6
// speedup vs baseline: 1.9839x; 1.6559x over previous
#include <cuda_runtime.h>
#include <cuda_bf16.h>
#include <cstdint>

// Problem constants (fixed by the reference)
#define NNODES 50000
#define NEDGES 400000
#define CH     256
#define K1     512
#define K2     256

// ---------------------------------------------------------------------------
// Scratch (__device__ globals; no allocations)
// ---------------------------------------------------------------------------
__device__ float    g_h1[(size_t)NNODES * CH];      // GEMM1 out
__device__ float    g_hr[(size_t)NNODES * CH];      // layer-1 activation
__device__ float    g_h2[(size_t)NNODES * CH];      // GEMM2 out
__device__ float    g_dinv[NNODES];
__device__ int      g_ideg[NNODES];
__device__ int      g_rowptr[NNODES + 1];
__device__ int      g_cursor[NNODES];
__device__ int      g_esrc[NEDGES];
__device__ int      g_is64;

// bf16 hi/lo pre-converted operands (u32 = packed bf16x2)
__device__ uint32_t g_xhi[(size_t)NNODES * K1 / 2];
__device__ uint32_t g_xlo[(size_t)NNODES * K1 / 2];
__device__ uint32_t g_hrhi[(size_t)NNODES * K2 / 2];
__device__ uint32_t g_hrlo[(size_t)NNODES * K2 / 2];
__device__ uint32_t g_w1hi[CH * K1 / 2];
__device__ uint32_t g_w1lo[CH * K1 / 2];
__device__ uint32_t g_w2hi[CH * K2 / 2];
__device__ uint32_t g_w2lo[CH * K2 / 2];

// ---------------------------------------------------------------------------
// Helpers
// ---------------------------------------------------------------------------
__device__ __forceinline__ uint32_t smem_u32(const void* p) {
    uint32_t a;
    asm("{ .reg .u64 t; cvta.to.shared.u64 t, %1; cvt.u32.u64 %0, t; }" : "=r"(a) : "l"(p));
    return a;
}

#define SW128(o) ((o) ^ (((o) >> 3) & 0x70))

__device__ __forceinline__ void ldsm4(uint32_t* r, uint32_t addr) {
    asm volatile("ldmatrix.sync.aligned.m8n8.x4.shared.b16 {%0,%1,%2,%3}, [%4];"
                 : "=r"(r[0]), "=r"(r[1]), "=r"(r[2]), "=r"(r[3]) : "r"(addr));
}

__device__ __forceinline__ void mma16816(float* c, const uint32_t* a,
                                         uint32_t b0, uint32_t b1) {
    asm volatile(
        "mma.sync.aligned.m16n8k16.row.col.f32.bf16.bf16.f32 "
        "{%0,%1,%2,%3}, {%4,%5,%6,%7}, {%8,%9}, {%0,%1,%2,%3};"
        : "+f"(c[0]), "+f"(c[1]), "+f"(c[2]), "+f"(c[3])
        : "r"(a[0]), "r"(a[1]), "r"(a[2]), "r"(a[3]), "r"(b0), "r"(b1));
}

#define STS128W(addr, w0, w1, w2, w3) \
    asm volatile("st.shared.v4.b32 [%0], {%1,%2,%3,%4};" \
                 :: "r"(addr), "r"(w0), "r"(w1), "r"(w2), "r"(w3) : "memory")

// Split two fp32 into bf16x2 hi-word + residual bf16x2 lo-word
__device__ __forceinline__ void bsplit2(float x0, float x1, uint32_t& hi, uint32_t& lo) {
    __nv_bfloat16 h0 = __float2bfloat16_rn(x0);
    __nv_bfloat16 h1 = __float2bfloat16_rn(x1);
    float r0 = x0 - __bfloat162float(h0);
    float r1 = x1 - __bfloat162float(h1);
    __nv_bfloat162 hp, lp;
    hp.x = h0; hp.y = h1;
    lp.x = __float2bfloat16_rn(r0); lp.y = __float2bfloat16_rn(r1);
    hi = *reinterpret_cast<uint32_t*>(&hp);
    lo = *reinterpret_cast<uint32_t*>(&lp);
}

// ---------------------------------------------------------------------------
// Conversion kernels: fp32 -> bf16 hi/lo, 8 floats per thread
// ---------------------------------------------------------------------------
__device__ __forceinline__ void conv_body(const float* __restrict__ in,
                                          uint32_t* __restrict__ hi,
                                          uint32_t* __restrict__ lo, int n8)
{
    int idx = blockIdx.x * blockDim.x + threadIdx.x;
    if (idx >= n8) return;
    const float* p = in + (size_t)idx * 8;
    float4 a = *(const float4*)p;
    float4 b = *(const float4*)(p + 4);
    uint32_t h0, l0, h1, l1, h2, l2, h3, l3;
    bsplit2(a.x, a.y, h0, l0);  bsplit2(a.z, a.w, h1, l1);
    bsplit2(b.x, b.y, h2, l2);  bsplit2(b.z, b.w, h3, l3);
    *(uint4*)&hi[(size_t)idx * 4] = make_uint4(h0, h1, h2, h3);
    *(uint4*)&lo[(size_t)idx * 4] = make_uint4(l0, l1, l2, l3);
}

__global__ void k_conv_x(const float* __restrict__ x) {
    conv_body(x, g_xhi, g_xlo, NNODES * K1 / 8);
}
__global__ void k_conv_w1(const float* __restrict__ w) {
    conv_body(w, g_w1hi, g_w1lo, CH * K1 / 8);
}
__global__ void k_conv_w2(const float* __restrict__ w) {
    conv_body(w, g_w2hi, g_w2lo, CH * K2 / 8);
}
__global__ void k_conv_hr() {
    conv_body(g_hr, g_hrhi, g_hrlo, NNODES * K2 / 8);
}

// ---------------------------------------------------------------------------
// bf16 split-3 GEMM on pre-converted inputs.
// C[M,256] = A[M,K] @ B[256,K]^T. CTA tile 128x128, BK=64, 256 threads.
// smem: aHi | aLo | bHi | bLo, each 128 rows x 128B SW128 = 64KB.
// ---------------------------------------------------------------------------
#define GEMM_SMEM (64 * 1024)

__device__ __forceinline__ void mma_gemm_body(
    const uint32_t* __restrict__ Ahi, const uint32_t* __restrict__ Alo,
    const uint32_t* __restrict__ Bhi, const uint32_t* __restrict__ Blo,
    float* __restrict__ C, int M, int K)
{
    extern __shared__ char dsm_raw[];
    const uint32_t base = smem_u32(dsm_raw);
    const uint32_t aHi = base;
    const uint32_t aLo = base + 16384;
    const uint32_t bHi = base + 32768;
    const uint32_t bLo = base + 49152;

    const int t    = threadIdx.x;
    const int wid  = t >> 5;
    const int lane = t & 31;
    const int brow = blockIdx.x * 128;
    const int bcol = blockIdx.y * 128;

    const int warp_m = (wid >> 1) * 32;   // 0,32,64,96
    const int warp_n = (wid & 1) * 64;    // 0,64

    float acc[2][8][4];
#pragma unroll
    for (int i = 0; i < 2; i++)
#pragma unroll
        for (int j = 0; j < 8; j++)
#pragma unroll
            for (int q = 0; q < 4; q++) acc[i][j][q] = 0.0f;

    const int lr  = lane & 15;
    const int kh  = lane >> 4;

    const int nch = K >> 6;
    for (int c = 0; c < nch; c++) {
        const int k0 = c << 6;

        // A tile: 128 rows x 64 elems; item = 8 bf16 = 1 uint4 per hi/lo.
        // 1024 items: r = g>>3, j = g&7
#pragma unroll
        for (int it = 0; it < 4; it++) {
            int g = t + it * 256;
            int r = g >> 3, j = g & 7;
            int gr = brow + r;
            uint4 vh = make_uint4(0, 0, 0, 0), vl = vh;
            if (gr < M) {
                size_t e = ((size_t)gr * K + k0 + j * 8) >> 1;   // u32 index
                vh = *(const uint4*)&Ahi[e];
                vl = *(const uint4*)&Alo[e];
            }
            uint32_t off = SW128((uint32_t)(r * 128 + j * 16));
            STS128W(aHi + off, vh.x, vh.y, vh.z, vh.w);
            STS128W(aLo + off, vl.x, vl.y, vl.z, vl.w);
        }
        // B tile: rows bcol..bcol+127
#pragma unroll
        for (int it = 0; it < 4; it++) {
            int g = t + it * 256;
            int r = g >> 3, j = g & 7;
            size_t e = ((size_t)(bcol + r) * K + k0 + j * 8) >> 1;
            uint4 vh = *(const uint4*)&Bhi[e];
            uint4 vl = *(const uint4*)&Blo[e];
            uint32_t off = SW128((uint32_t)(r * 128 + j * 16));
            STS128W(bHi + off, vh.x, vh.y, vh.z, vh.w);
            STS128W(bLo + off, vl.x, vl.y, vl.z, vl.w);
        }
        __syncthreads();

#pragma unroll
        for (int s = 0; s < 4; s++) {
            const int jg = s * 2 + kh;

            uint32_t ah[2][4], bh[4][4];
#pragma unroll
            for (int mi = 0; mi < 2; mi++) {
                int r = warp_m + mi * 16 + lr;
                ldsm4(ah[mi], aHi + (uint32_t)(r * 128 + ((jg ^ (r & 7)) << 4)));
            }
#pragma unroll
            for (int nj = 0; nj < 4; nj++) {
                int r = warp_n + nj * 16 + lr;
                ldsm4(bh[nj], bHi + (uint32_t)(r * 128 + ((jg ^ (r & 7)) << 4)));
            }
            // hi*hi
#pragma unroll
            for (int mi = 0; mi < 2; mi++)
#pragma unroll
                for (int nj = 0; nj < 4; nj++) {
                    mma16816(acc[mi][nj * 2 + 0], ah[mi], bh[nj][0], bh[nj][2]);
                    mma16816(acc[mi][nj * 2 + 1], ah[mi], bh[nj][1], bh[nj][3]);
                }
            // lo*hi
            {
                uint32_t al[2][4];
#pragma unroll
                for (int mi = 0; mi < 2; mi++) {
                    int r = warp_m + mi * 16 + lr;
                    ldsm4(al[mi], aLo + (uint32_t)(r * 128 + ((jg ^ (r & 7)) << 4)));
                }
#pragma unroll
                for (int mi = 0; mi < 2; mi++)
#pragma unroll
                    for (int nj = 0; nj < 4; nj++) {
                        mma16816(acc[mi][nj * 2 + 0], al[mi], bh[nj][0], bh[nj][2]);
                        mma16816(acc[mi][nj * 2 + 1], al[mi], bh[nj][1], bh[nj][3]);
                    }
            }
            // hi*lo
            {
                uint32_t bl[4][4];
#pragma unroll
                for (int nj = 0; nj < 4; nj++) {
                    int r = warp_n + nj * 16 + lr;
                    ldsm4(bl[nj], bLo + (uint32_t)(r * 128 + ((jg ^ (r & 7)) << 4)));
                }
#pragma unroll
                for (int mi = 0; mi < 2; mi++)
#pragma unroll
                    for (int nj = 0; nj < 4; nj++) {
                        mma16816(acc[mi][nj * 2 + 0], ah[mi], bl[nj][0], bl[nj][2]);
                        mma16816(acc[mi][nj * 2 + 1], ah[mi], bl[nj][1], bl[nj][3]);
                    }
            }
        }
        __syncthreads();
    }

    // epilogue
    const int qr = lane >> 2;
    const int qc = (lane & 3) * 2;
#pragma unroll
    for (int mi = 0; mi < 2; mi++) {
        int r0 = brow + warp_m + mi * 16 + qr;
#pragma unroll
        for (int n8 = 0; n8 < 8; n8++) {
            int col = bcol + warp_n + n8 * 8 + qc;
            if (r0 < M) {
                float2 v = make_float2(acc[mi][n8][0], acc[mi][n8][1]);
                *(float2*)&C[(size_t)r0 * 256 + col] = v;
            }
            if (r0 + 8 < M) {
                float2 v = make_float2(acc[mi][n8][2], acc[mi][n8][3]);
                *(float2*)&C[(size_t)(r0 + 8) * 256 + col] = v;
            }
        }
    }
}

__global__ void __launch_bounds__(256)
k_mmagemm1() { mma_gemm_body(g_xhi, g_xlo, g_w1hi, g_w1lo, g_h1, NNODES, K1); }
__global__ void __launch_bounds__(256)
k_mmagemm2() { mma_gemm_body(g_hrhi, g_hrlo, g_w2hi, g_w2lo, g_h2, NNODES, K2); }

// ---------------------------------------------------------------------------
// edge_index dtype detection (int64 per spec; tolerate int32)
// ---------------------------------------------------------------------------
__global__ void k_detect(const long long* __restrict__ ei) {
    if (blockIdx.x == 0 && threadIdx.x == 0) {
        int is64 = 1;
        for (int i = 0; i < 256; i++) {
            long long v = ei[i];
            if (v < 0 || v >= NNODES) { is64 = 0; break; }
        }
        g_is64 = is64;
    }
}

__device__ __forceinline__ int edge_idx(const void* ei, int half, int e) {
    if (g_is64) return (int)((const long long*)ei)[(size_t)half * NEDGES + e];
    return ((const int*)ei)[(size_t)half * NEDGES + e];
}

// ---------------------------------------------------------------------------
// CSR build: in-degree -> scan -> bucket fill
// ---------------------------------------------------------------------------
__global__ void k_zero_ideg() {
    int i = blockIdx.x * blockDim.x + threadIdx.x;
    if (i < NNODES) g_ideg[i] = 0;
}

__global__ void k_count(const void* __restrict__ ei) {
    int e = blockIdx.x * blockDim.x + threadIdx.x;
    if (e < NEDGES) atomicAdd(&g_ideg[edge_idx(ei, 1, e)], 1);
}

__global__ void k_dinv() {
    int i = blockIdx.x * blockDim.x + threadIdx.x;
    if (i < NNODES) g_dinv[i] = rsqrtf(1.0f + (float)g_ideg[i]);
}

// single-block exclusive scan of in-degrees -> rowptr, cursor
#define SCAN_T 1024
#define SCAN_C ((NNODES + SCAN_T - 1) / SCAN_T)   // 49
__global__ void __launch_bounds__(SCAN_T)
k_scan() {
    __shared__ int part[SCAN_T];
    const int t = threadIdx.x;
    const int start = t * SCAN_C;
    const int end   = min(start + SCAN_C, NNODES);
    int s = 0;
    for (int i = start; i < end; i++) s += g_ideg[i];
    part[t] = s;
    __syncthreads();
    // Hillis-Steele inclusive scan
    for (int off = 1; off < SCAN_T; off <<= 1) {
        int v = (t >= off) ? part[t - off] : 0;
        __syncthreads();
        part[t] += v;
        __syncthreads();
    }
    int run = part[t] - s;          // exclusive base for this chunk
    for (int i = start; i < end; i++) {
        g_rowptr[i] = run;
        g_cursor[i] = run;
        run += g_ideg[i];
    }
    if (t == SCAN_T - 1) g_rowptr[NNODES] = part[SCAN_T - 1];
}

__global__ void k_fill(const void* __restrict__ ei) {
    int e = blockIdx.x * blockDim.x + threadIdx.x;
    if (e >= NEDGES) return;
    int s = edge_idx(ei, 0, e);
    int d = edge_idx(ei, 1, e);
    int pos = atomicAdd(&g_cursor[d], 1);
    g_esrc[pos] = s;
}

// ---------------------------------------------------------------------------
// Gather aggregation: one warp per node.
// out[d,:] = (relu?)( h[d,:]*dinv[d]^2 + sum_in h[s,:]*dinv[s]*dinv[d] + b )
// ---------------------------------------------------------------------------
template <bool RELU>
__device__ __forceinline__ void gather_body(
    const float* __restrict__ h, const float* __restrict__ bias,
    float* __restrict__ out)
{
    const int wid  = threadIdx.x >> 5;
    const int lane = threadIdx.x & 31;
    const int node = blockIdx.x * 8 + wid;
    if (node >= NNODES) return;

    const float dv = g_dinv[node];
    const float* hd = h + (size_t)node * CH;
    float4 a0 = *(const float4*)&hd[lane * 4];
    float4 a1 = *(const float4*)&hd[128 + lane * 4];
    const float sv = dv * dv;
    a0.x *= sv; a0.y *= sv; a0.z *= sv; a0.w *= sv;
    a1.x *= sv; a1.y *= sv; a1.z *= sv; a1.w *= sv;

    const int p0 = g_rowptr[node];
    const int p1 = g_rowptr[node + 1];
    for (int p = p0; p < p1; p++) {
        int s = g_esrc[p];
        float w = g_dinv[s] * dv;
        const float* hs = h + (size_t)s * CH;
        float4 v0 = *(const float4*)&hs[lane * 4];
        float4 v1 = *(const float4*)&hs[128 + lane * 4];
        a0.x = fmaf(v0.x, w, a0.x); a0.y = fmaf(v0.y, w, a0.y);
        a0.z = fmaf(v0.z, w, a0.z); a0.w = fmaf(v0.w, w, a0.w);
        a1.x = fmaf(v1.x, w, a1.x); a1.y = fmaf(v1.y, w, a1.y);
        a1.z = fmaf(v1.z, w, a1.z); a1.w = fmaf(v1.w, w, a1.w);
    }

    const float4 b0 = *(const float4*)&bias[lane * 4];
    const float4 b1 = *(const float4*)&bias[128 + lane * 4];
    a0.x += b0.x; a0.y += b0.y; a0.z += b0.z; a0.w += b0.w;
    a1.x += b1.x; a1.y += b1.y; a1.z += b1.z; a1.w += b1.w;
    if (RELU) {
        a0.x = fmaxf(a0.x, 0.f); a0.y = fmaxf(a0.y, 0.f);
        a0.z = fmaxf(a0.z, 0.f); a0.w = fmaxf(a0.w, 0.f);
        a1.x = fmaxf(a1.x, 0.f); a1.y = fmaxf(a1.y, 0.f);
        a1.z = fmaxf(a1.z, 0.f); a1.w = fmaxf(a1.w, 0.f);
    }
    float* od = out + (size_t)node * CH;
    *(float4*)&od[lane * 4]       = a0;
    *(float4*)&od[128 + lane * 4] = a1;
}

__global__ void __launch_bounds__(256)
k_gather1(const float* __restrict__ b1) { gather_body<true>(g_h1, b1, g_hr); }
__global__ void __launch_bounds__(256)
k_gather2(const float* __restrict__ b2, float* __restrict__ out) {
    gather_body<false>(g_h2, b2, out);
}

// ---------------------------------------------------------------------------
// Launch
// ---------------------------------------------------------------------------
extern "C" void kernel_launch(void* const* d_in, const int* in_sizes, int n_in,
                              void* d_out, int out_size)
{
    const float* x   = (const float*)d_in[0];
    const void*  ei  = d_in[1];
    const float* W1  = (const float*)d_in[2];
    const float* b1  = (const float*)d_in[3];
    const float* W2  = (const float*)d_in[4];
    const float* b2  = (const float*)d_in[5];
    float*       out = (float*)d_out;

    static bool attr_done = false;
    if (!attr_done) {
        cudaFuncSetAttribute(k_mmagemm1, cudaFuncAttributeMaxDynamicSharedMemorySize, GEMM_SMEM);
        cudaFuncSetAttribute(k_mmagemm2, cudaFuncAttributeMaxDynamicSharedMemorySize, GEMM_SMEM);
        attr_done = true;
    }

    const int NTH = 256;
    const int nblk_nodes = (NNODES + NTH - 1) / NTH;
    const int nblk_edges = (NEDGES + NTH - 1) / NTH;
    const int nblk_gather = (NNODES + 7) / 8;

    dim3 gg((NNODES + 127) / 128, 2);

    // dtype detection + CSR + dinv
    k_detect<<<1, 32>>>((const long long*)ei);
    k_zero_ideg<<<nblk_nodes, NTH>>>();
    k_count<<<nblk_edges, NTH>>>(ei);
    k_dinv<<<nblk_nodes, NTH>>>();
    k_scan<<<1, SCAN_T>>>();
    k_fill<<<nblk_edges, NTH>>>(ei);

    // pre-conversion (x, W1, W2)
    k_conv_x<<<(NNODES * K1 / 8 + NTH - 1) / NTH, NTH>>>(x);
    k_conv_w1<<<(CH * K1 / 8 + NTH - 1) / NTH, NTH>>>(W1);
    k_conv_w2<<<(CH * K2 / 8 + NTH - 1) / NTH, NTH>>>(W2);

    // layer 1
    k_mmagemm1<<<gg, NTH, GEMM_SMEM>>>();
    k_gather1<<<nblk_gather, NTH>>>(b1);

    // layer 2
    k_conv_hr<<<(NNODES * K2 / 8 + NTH - 1) / NTH, NTH>>>();
    k_mmagemm2<<<gg, NTH, GEMM_SMEM>>>();
    k_gather2<<<nblk_gather, NTH>>>(b2, out);
}

// round 7
// speedup vs baseline: 2.2170x; 1.1175x over previous
#include <cuda_runtime.h>
#include <cuda_bf16.h>
#include <cstdint>

// Problem constants (fixed by the reference)
#define NNODES 50000
#define NEDGES 400000
#define CH     256
#define K1     512
#define K2     256

// ---------------------------------------------------------------------------
// Scratch (__device__ globals; no allocations)
// ---------------------------------------------------------------------------
__device__ float    g_h1[(size_t)NNODES * CH];      // GEMM1 out
__device__ float    g_h2[(size_t)NNODES * CH];      // GEMM2 out
__device__ float    g_dinv[NNODES];
__device__ int      g_ideg[NNODES];
__device__ int      g_rowptr[NNODES + 1];
__device__ int      g_cursor[NNODES];
__device__ int      g_esrc[NEDGES];
__device__ int      g_is64;

// bf16 hi/lo pre-converted operands (u32 = packed bf16x2)
__device__ uint32_t g_xhi[(size_t)NNODES * K1 / 2];
__device__ uint32_t g_xlo[(size_t)NNODES * K1 / 2];
__device__ uint32_t g_hrhi[(size_t)NNODES * K2 / 2];
__device__ uint32_t g_hrlo[(size_t)NNODES * K2 / 2];
__device__ uint32_t g_w1hi[CH * K1 / 2];
__device__ uint32_t g_w1lo[CH * K1 / 2];
__device__ uint32_t g_w2hi[CH * K2 / 2];
__device__ uint32_t g_w2lo[CH * K2 / 2];

// ---------------------------------------------------------------------------
// Helpers
// ---------------------------------------------------------------------------
__device__ __forceinline__ uint32_t smem_u32(const void* p) {
    uint32_t a;
    asm("{ .reg .u64 t; cvta.to.shared.u64 t, %1; cvt.u32.u64 %0, t; }" : "=r"(a) : "l"(p));
    return a;
}

#define SW128(o) ((o) ^ (((o) >> 3) & 0x70))

__device__ __forceinline__ void ldsm4(uint32_t* r, uint32_t addr) {
    asm volatile("ldmatrix.sync.aligned.m8n8.x4.shared.b16 {%0,%1,%2,%3}, [%4];"
                 : "=r"(r[0]), "=r"(r[1]), "=r"(r[2]), "=r"(r[3]) : "r"(addr));
}

__device__ __forceinline__ void mma16816(float* c, const uint32_t* a,
                                         uint32_t b0, uint32_t b1) {
    asm volatile(
        "mma.sync.aligned.m16n8k16.row.col.f32.bf16.bf16.f32 "
        "{%0,%1,%2,%3}, {%4,%5,%6,%7}, {%8,%9}, {%0,%1,%2,%3};"
        : "+f"(c[0]), "+f"(c[1]), "+f"(c[2]), "+f"(c[3])
        : "r"(a[0]), "r"(a[1]), "r"(a[2]), "r"(a[3]), "r"(b0), "r"(b1));
}

__device__ __forceinline__ void cpa16(uint32_t dst, const void* src, uint32_t srcsz) {
    asm volatile("cp.async.cg.shared.global [%0], [%1], 16, %2;"
                 :: "r"(dst), "l"(src), "r"(srcsz) : "memory");
}
#define CPA_COMMIT() asm volatile("cp.async.commit_group;" ::: "memory")
#define CPA_WAIT(N)  asm volatile("cp.async.wait_group %0;" :: "n"(N) : "memory")

// Split two fp32 into bf16x2 hi-word + residual bf16x2 lo-word
__device__ __forceinline__ void bsplit2(float x0, float x1, uint32_t& hi, uint32_t& lo) {
    __nv_bfloat16 h0 = __float2bfloat16_rn(x0);
    __nv_bfloat16 h1 = __float2bfloat16_rn(x1);
    float r0 = x0 - __bfloat162float(h0);
    float r1 = x1 - __bfloat162float(h1);
    __nv_bfloat162 hp, lp;
    hp.x = h0; hp.y = h1;
    lp.x = __float2bfloat16_rn(r0); lp.y = __float2bfloat16_rn(r1);
    hi = *reinterpret_cast<uint32_t*>(&hp);
    lo = *reinterpret_cast<uint32_t*>(&lp);
}

// ---------------------------------------------------------------------------
// Conversion kernels: fp32 -> bf16 hi/lo, 8 floats per thread
// ---------------------------------------------------------------------------
__device__ __forceinline__ void conv_body(const float* __restrict__ in,
                                          uint32_t* __restrict__ hi,
                                          uint32_t* __restrict__ lo, int n8)
{
    int idx = blockIdx.x * blockDim.x + threadIdx.x;
    if (idx >= n8) return;
    const float* p = in + (size_t)idx * 8;
    float4 a = *(const float4*)p;
    float4 b = *(const float4*)(p + 4);
    uint32_t h0, l0, h1, l1, h2, l2, h3, l3;
    bsplit2(a.x, a.y, h0, l0);  bsplit2(a.z, a.w, h1, l1);
    bsplit2(b.x, b.y, h2, l2);  bsplit2(b.z, b.w, h3, l3);
    *(uint4*)&hi[(size_t)idx * 4] = make_uint4(h0, h1, h2, h3);
    *(uint4*)&lo[(size_t)idx * 4] = make_uint4(l0, l1, l2, l3);
}

__global__ void k_conv_x(const float* __restrict__ x) {
    conv_body(x, g_xhi, g_xlo, NNODES * K1 / 8);
}
__global__ void k_conv_w1(const float* __restrict__ w) {
    conv_body(w, g_w1hi, g_w1lo, CH * K1 / 8);
}
__global__ void k_conv_w2(const float* __restrict__ w) {
    conv_body(w, g_w2hi, g_w2lo, CH * K2 / 8);
}

// ---------------------------------------------------------------------------
// bf16 split-3 GEMM, cp.async 2-stage pipeline.
// C[M,256] = A[M,K] @ B[256,K]^T. CTA tile 128x128, BK=32, 256 threads.
// Row layout (128B, SW128): [hi: 32 bf16 = 64B | lo: 32 bf16 = 64B]
//   -> hi fragments in 16B-groups j=0..3, lo in j=4..7.
// Stage = A(16KB) + B(16KB) = 32KB; two stages = 64KB.
// ---------------------------------------------------------------------------
#define GEMM_SMEM (64 * 1024)

__device__ __forceinline__ void load_chunk(
    const uint32_t* __restrict__ Ahi, const uint32_t* __restrict__ Alo,
    const uint32_t* __restrict__ Bhi, const uint32_t* __restrict__ Blo,
    uint32_t bufA, uint32_t bufB,
    int brow, int bcol, int M, int K, int k0, int t)
{
#pragma unroll
    for (int it = 0; it < 4; it++) {
        int g = t + it * 256;              // 0..1023
        int r = g >> 3, j = g & 7;
        int gr = brow + r;
        const uint32_t* src = (j < 4) ? Ahi : Alo;
        int koff = (j & 3) * 8;
        const void* p = &src[((size_t)gr * K + k0 + koff) >> 1];
        cpa16(bufA + SW128((uint32_t)(r * 128 + j * 16)), p, gr < M ? 16u : 0u);
    }
#pragma unroll
    for (int it = 0; it < 4; it++) {
        int g = t + it * 256;
        int r = g >> 3, j = g & 7;
        const uint32_t* src = (j < 4) ? Bhi : Blo;
        int koff = (j & 3) * 8;
        const void* p = &src[((size_t)(bcol + r) * K + k0 + koff) >> 1];
        cpa16(bufB + SW128((uint32_t)(r * 128 + j * 16)), p, 16u);
    }
}

__device__ __forceinline__ void mma_gemm_body(
    const uint32_t* __restrict__ Ahi, const uint32_t* __restrict__ Alo,
    const uint32_t* __restrict__ Bhi, const uint32_t* __restrict__ Blo,
    float* __restrict__ C, int M, int K)
{
    extern __shared__ char dsm_raw[];
    const uint32_t base = smem_u32(dsm_raw);

    const int t    = threadIdx.x;
    const int wid  = t >> 5;
    const int lane = t & 31;
    const int brow = blockIdx.x * 128;
    const int bcol = blockIdx.y * 128;

    const int warp_m = (wid >> 1) * 32;   // 0,32,64,96
    const int warp_n = (wid & 1) * 64;    // 0,64

    float acc[2][8][4];
#pragma unroll
    for (int i = 0; i < 2; i++)
#pragma unroll
        for (int j = 0; j < 8; j++)
#pragma unroll
            for (int q = 0; q < 4; q++) acc[i][j][q] = 0.0f;

    const int lr = lane & 15;
    const int kh = lane >> 4;

    const int nch = K >> 5;

    // prologue: chunk 0 -> stage 0
    load_chunk(Ahi, Alo, Bhi, Blo, base, base + 16384, brow, bcol, M, K, 0, t);
    CPA_COMMIT();

    for (int c = 0; c < nch; c++) {
        const uint32_t cur = (c & 1) ? base + 32768 : base;
        if (c + 1 < nch) {
            const uint32_t nxt = ((c + 1) & 1) ? base + 32768 : base;
            load_chunk(Ahi, Alo, Bhi, Blo, nxt, nxt + 16384,
                       brow, bcol, M, K, (c + 1) << 5, t);
            CPA_COMMIT();
            CPA_WAIT(1);
        } else {
            CPA_WAIT(0);
        }
        __syncthreads();

        const uint32_t curA = cur;
        const uint32_t curB = cur + 16384;

#pragma unroll
        for (int s = 0; s < 2; s++) {
            const int jh = s * 2 + kh;     // hi groups 0..3
            const int jl = jh + 4;         // lo groups 4..7

            uint32_t ah[2][4], bh[4][4];
#pragma unroll
            for (int mi = 0; mi < 2; mi++) {
                int r = warp_m + mi * 16 + lr;
                ldsm4(ah[mi], curA + (uint32_t)(r * 128 + ((jh ^ (r & 7)) << 4)));
            }
#pragma unroll
            for (int nj = 0; nj < 4; nj++) {
                int r = warp_n + nj * 16 + lr;
                ldsm4(bh[nj], curB + (uint32_t)(r * 128 + ((jh ^ (r & 7)) << 4)));
            }
            // hi*hi
#pragma unroll
            for (int mi = 0; mi < 2; mi++)
#pragma unroll
                for (int nj = 0; nj < 4; nj++) {
                    mma16816(acc[mi][nj * 2 + 0], ah[mi], bh[nj][0], bh[nj][2]);
                    mma16816(acc[mi][nj * 2 + 1], ah[mi], bh[nj][1], bh[nj][3]);
                }
            // lo*hi
            {
                uint32_t al[2][4];
#pragma unroll
                for (int mi = 0; mi < 2; mi++) {
                    int r = warp_m + mi * 16 + lr;
                    ldsm4(al[mi], curA + (uint32_t)(r * 128 + ((jl ^ (r & 7)) << 4)));
                }
#pragma unroll
                for (int mi = 0; mi < 2; mi++)
#pragma unroll
                    for (int nj = 0; nj < 4; nj++) {
                        mma16816(acc[mi][nj * 2 + 0], al[mi], bh[nj][0], bh[nj][2]);
                        mma16816(acc[mi][nj * 2 + 1], al[mi], bh[nj][1], bh[nj][3]);
                    }
            }
            // hi*lo
            {
                uint32_t bl[4][4];
#pragma unroll
                for (int nj = 0; nj < 4; nj++) {
                    int r = warp_n + nj * 16 + lr;
                    ldsm4(bl[nj], curB + (uint32_t)(r * 128 + ((jl ^ (r & 7)) << 4)));
                }
#pragma unroll
                for (int mi = 0; mi < 2; mi++)
#pragma unroll
                    for (int nj = 0; nj < 4; nj++) {
                        mma16816(acc[mi][nj * 2 + 0], ah[mi], bl[nj][0], bl[nj][2]);
                        mma16816(acc[mi][nj * 2 + 1], ah[mi], bl[nj][1], bl[nj][3]);
                    }
            }
        }
        __syncthreads();
    }

    // epilogue
    const int qr = lane >> 2;
    const int qc = (lane & 3) * 2;
#pragma unroll
    for (int mi = 0; mi < 2; mi++) {
        int r0 = brow + warp_m + mi * 16 + qr;
#pragma unroll
        for (int n8 = 0; n8 < 8; n8++) {
            int col = bcol + warp_n + n8 * 8 + qc;
            if (r0 < M) {
                float2 v = make_float2(acc[mi][n8][0], acc[mi][n8][1]);
                *(float2*)&C[(size_t)r0 * 256 + col] = v;
            }
            if (r0 + 8 < M) {
                float2 v = make_float2(acc[mi][n8][2], acc[mi][n8][3]);
                *(float2*)&C[(size_t)(r0 + 8) * 256 + col] = v;
            }
        }
    }
}

__global__ void __launch_bounds__(256)
k_mmagemm1() { mma_gemm_body(g_xhi, g_xlo, g_w1hi, g_w1lo, g_h1, NNODES, K1); }
__global__ void __launch_bounds__(256)
k_mmagemm2() { mma_gemm_body(g_hrhi, g_hrlo, g_w2hi, g_w2lo, g_h2, NNODES, K2); }

// ---------------------------------------------------------------------------
// edge_index dtype detection (int64 per spec; tolerate int32)
// ---------------------------------------------------------------------------
__global__ void k_detect(const long long* __restrict__ ei) {
    if (blockIdx.x == 0 && threadIdx.x == 0) {
        int is64 = 1;
        for (int i = 0; i < 256; i++) {
            long long v = ei[i];
            if (v < 0 || v >= NNODES) { is64 = 0; break; }
        }
        g_is64 = is64;
    }
}

__device__ __forceinline__ int edge_idx(const void* ei, int half, int e) {
    if (g_is64) return (int)((const long long*)ei)[(size_t)half * NEDGES + e];
    return ((const int*)ei)[(size_t)half * NEDGES + e];
}

// ---------------------------------------------------------------------------
// CSR build: in-degree -> scan -> bucket fill
// ---------------------------------------------------------------------------
__global__ void k_zero_ideg() {
    int i = blockIdx.x * blockDim.x + threadIdx.x;
    if (i < NNODES) g_ideg[i] = 0;
}

__global__ void k_count(const void* __restrict__ ei) {
    int e = blockIdx.x * blockDim.x + threadIdx.x;
    if (e < NEDGES) atomicAdd(&g_ideg[edge_idx(ei, 1, e)], 1);
}

__global__ void k_dinv() {
    int i = blockIdx.x * blockDim.x + threadIdx.x;
    if (i < NNODES) g_dinv[i] = rsqrtf(1.0f + (float)g_ideg[i]);
}

#define SCAN_T 1024
#define SCAN_C ((NNODES + SCAN_T - 1) / SCAN_T)
__global__ void __launch_bounds__(SCAN_T)
k_scan() {
    __shared__ int part[SCAN_T];
    const int t = threadIdx.x;
    const int start = t * SCAN_C;
    const int end   = min(start + SCAN_C, NNODES);
    int s = 0;
    for (int i = start; i < end; i++) s += g_ideg[i];
    part[t] = s;
    __syncthreads();
    for (int off = 1; off < SCAN_T; off <<= 1) {
        int v = (t >= off) ? part[t - off] : 0;
        __syncthreads();
        part[t] += v;
        __syncthreads();
    }
    int run = part[t] - s;
    for (int i = start; i < end; i++) {
        g_rowptr[i] = run;
        g_cursor[i] = run;
        run += g_ideg[i];
    }
    if (t == SCAN_T - 1) g_rowptr[NNODES] = part[SCAN_T - 1];
}

__global__ void k_fill(const void* __restrict__ ei) {
    int e = blockIdx.x * blockDim.x + threadIdx.x;
    if (e >= NEDGES) return;
    int s = edge_idx(ei, 0, e);
    int d = edge_idx(ei, 1, e);
    int pos = atomicAdd(&g_cursor[d], 1);
    g_esrc[pos] = s;
}

// ---------------------------------------------------------------------------
// Gather aggregation: one warp per node.
// ---------------------------------------------------------------------------
__device__ __forceinline__ void gather_acc(
    const float* __restrict__ h, const float* __restrict__ bias,
    int node, int lane, float4& a0, float4& a1)
{
    const float dv = g_dinv[node];
    const float* hd = h + (size_t)node * CH;
    a0 = *(const float4*)&hd[lane * 4];
    a1 = *(const float4*)&hd[128 + lane * 4];
    const float sv = dv * dv;
    a0.x *= sv; a0.y *= sv; a0.z *= sv; a0.w *= sv;
    a1.x *= sv; a1.y *= sv; a1.z *= sv; a1.w *= sv;

    const int p0 = g_rowptr[node];
    const int p1 = g_rowptr[node + 1];
    for (int p = p0; p < p1; p++) {
        int s = g_esrc[p];
        float w = g_dinv[s] * dv;
        const float* hs = h + (size_t)s * CH;
        float4 v0 = *(const float4*)&hs[lane * 4];
        float4 v1 = *(const float4*)&hs[128 + lane * 4];
        a0.x = fmaf(v0.x, w, a0.x); a0.y = fmaf(v0.y, w, a0.y);
        a0.z = fmaf(v0.z, w, a0.z); a0.w = fmaf(v0.w, w, a0.w);
        a1.x = fmaf(v1.x, w, a1.x); a1.y = fmaf(v1.y, w, a1.y);
        a1.z = fmaf(v1.z, w, a1.z); a1.w = fmaf(v1.w, w, a1.w);
    }

    const float4 b0 = *(const float4*)&bias[lane * 4];
    const float4 b1 = *(const float4*)&bias[128 + lane * 4];
    a0.x += b0.x; a0.y += b0.y; a0.z += b0.z; a0.w += b0.w;
    a1.x += b1.x; a1.y += b1.y; a1.z += b1.z; a1.w += b1.w;
}

// layer 1: relu then emit bf16 hi/lo split directly (GEMM2 input)
__global__ void __launch_bounds__(256)
k_gather1(const float* __restrict__ b1)
{
    const int wid  = threadIdx.x >> 5;
    const int lane = threadIdx.x & 31;
    const int node = blockIdx.x * 8 + wid;
    if (node >= NNODES) return;
    float4 a0, a1;
    gather_acc(g_h1, b1, node, lane, a0, a1);
    a0.x = fmaxf(a0.x, 0.f); a0.y = fmaxf(a0.y, 0.f);
    a0.z = fmaxf(a0.z, 0.f); a0.w = fmaxf(a0.w, 0.f);
    a1.x = fmaxf(a1.x, 0.f); a1.y = fmaxf(a1.y, 0.f);
    a1.z = fmaxf(a1.z, 0.f); a1.w = fmaxf(a1.w, 0.f);

    uint32_t h0, l0, h1, l1;
    size_t bix = (size_t)node * 128 + lane * 2;
    bsplit2(a0.x, a0.y, h0, l0); bsplit2(a0.z, a0.w, h1, l1);
    *(uint2*)&g_hrhi[bix] = make_uint2(h0, h1);
    *(uint2*)&g_hrlo[bix] = make_uint2(l0, l1);
    bsplit2(a1.x, a1.y, h0, l0); bsplit2(a1.z, a1.w, h1, l1);
    *(uint2*)&g_hrhi[bix + 64] = make_uint2(h0, h1);
    *(uint2*)&g_hrlo[bix + 64] = make_uint2(l0, l1);
}

// layer 2: plain output
__global__ void __launch_bounds__(256)
k_gather2(const float* __restrict__ b2, float* __restrict__ out)
{
    const int wid  = threadIdx.x >> 5;
    const int lane = threadIdx.x & 31;
    const int node = blockIdx.x * 8 + wid;
    if (node >= NNODES) return;
    float4 a0, a1;
    gather_acc(g_h2, b2, node, lane, a0, a1);
    float* od = out + (size_t)node * CH;
    *(float4*)&od[lane * 4]       = a0;
    *(float4*)&od[128 + lane * 4] = a1;
}

// ---------------------------------------------------------------------------
// Launch
// ---------------------------------------------------------------------------
extern "C" void kernel_launch(void* const* d_in, const int* in_sizes, int n_in,
                              void* d_out, int out_size)
{
    const float* x   = (const float*)d_in[0];
    const void*  ei  = d_in[1];
    const float* W1  = (const float*)d_in[2];
    const float* b1  = (const float*)d_in[3];
    const float* W2  = (const float*)d_in[4];
    const float* b2  = (const float*)d_in[5];
    float*       out = (float*)d_out;

    static cudaStream_t s2 = nullptr;
    static cudaEvent_t  e0 = nullptr, e1 = nullptr;
    if (!s2) {
        cudaFuncSetAttribute(k_mmagemm1, cudaFuncAttributeMaxDynamicSharedMemorySize, GEMM_SMEM);
        cudaFuncSetAttribute(k_mmagemm2, cudaFuncAttributeMaxDynamicSharedMemorySize, GEMM_SMEM);
        cudaStreamCreateWithFlags(&s2, cudaStreamNonBlocking);
        cudaEventCreateWithFlags(&e0, cudaEventDisableTiming);
        cudaEventCreateWithFlags(&e1, cudaEventDisableTiming);
    }

    const int NTH = 256;
    const int nblk_nodes = (NNODES + NTH - 1) / NTH;
    const int nblk_edges = (NEDGES + NTH - 1) / NTH;
    const int nblk_gather = (NNODES + 7) / 8;

    dim3 gg((NNODES + 127) / 128, 2);

    // main stream: dtype detection, then fork CSR chain onto s2
    k_detect<<<1, 32>>>((const long long*)ei);
    cudaEventRecord(e0, 0);
    cudaStreamWaitEvent(s2, e0, 0);

    // s2: CSR + dinv (independent of GEMM1)
    k_zero_ideg<<<nblk_nodes, NTH, 0, s2>>>();
    k_count<<<nblk_edges, NTH, 0, s2>>>(ei);
    k_dinv<<<nblk_nodes, NTH, 0, s2>>>();
    k_scan<<<1, SCAN_T, 0, s2>>>();
    k_fill<<<nblk_edges, NTH, 0, s2>>>(ei);
    cudaEventRecord(e1, s2);

    // main: conversions + GEMM1 overlap the CSR build
    k_conv_x<<<(NNODES * K1 / 8 + NTH - 1) / NTH, NTH>>>(x);
    k_conv_w1<<<(CH * K1 / 8 + NTH - 1) / NTH, NTH>>>(W1);
    k_conv_w2<<<(CH * K2 / 8 + NTH - 1) / NTH, NTH>>>(W2);
    k_mmagemm1<<<gg, NTH, GEMM_SMEM>>>();

    // join: gather needs CSR + dinv
    cudaStreamWaitEvent(0, e1, 0);
    k_gather1<<<nblk_gather, NTH>>>(b1);

    // layer 2
    k_mmagemm2<<<gg, NTH, GEMM_SMEM>>>();
    k_gather2<<<nblk_gather, NTH>>>(b2, out);
}

// round 8
// speedup vs baseline: 2.4904x; 1.1233x over previous
#include <cuda_runtime.h>
#include <cuda_bf16.h>
#include <cstdint>

// Problem constants (fixed by the reference)
#define NNODES 50000
#define NEDGES 400000
#define CH     256
#define K1     512
#define K2     256

// ---------------------------------------------------------------------------
// Scratch (__device__ globals; no allocations)
// ---------------------------------------------------------------------------
__device__ float    g_h1[(size_t)NNODES * CH];      // GEMM1 out
__device__ float    g_h2[(size_t)NNODES * CH];      // GEMM2 out
__device__ float    g_dinv[NNODES];
__device__ int      g_ideg[NNODES];
__device__ int      g_rowptr[NNODES + 1];
__device__ int      g_cursor[NNODES];
__device__ int      g_esrc[NEDGES];
__device__ int      g_is64;

// bf16 hi/lo pre-converted operands (u32 = packed bf16x2)
__device__ uint32_t g_xhi[(size_t)NNODES * K1 / 2];
__device__ uint32_t g_xlo[(size_t)NNODES * K1 / 2];
__device__ uint32_t g_hrhi[(size_t)NNODES * K2 / 2];
__device__ uint32_t g_hrlo[(size_t)NNODES * K2 / 2];
__device__ uint32_t g_w1hi[CH * K1 / 2];
__device__ uint32_t g_w1lo[CH * K1 / 2];
__device__ uint32_t g_w2hi[CH * K2 / 2];
__device__ uint32_t g_w2lo[CH * K2 / 2];

// ---------------------------------------------------------------------------
// Helpers
// ---------------------------------------------------------------------------
__device__ __forceinline__ uint32_t smem_u32(const void* p) {
    uint32_t a;
    asm("{ .reg .u64 t; cvta.to.shared.u64 t, %1; cvt.u32.u64 %0, t; }" : "=r"(a) : "l"(p));
    return a;
}

#define SW128(o) ((o) ^ (((o) >> 3) & 0x70))

__device__ __forceinline__ void ldsm4(uint32_t* r, uint32_t addr) {
    asm volatile("ldmatrix.sync.aligned.m8n8.x4.shared.b16 {%0,%1,%2,%3}, [%4];"
                 : "=r"(r[0]), "=r"(r[1]), "=r"(r[2]), "=r"(r[3]) : "r"(addr));
}

__device__ __forceinline__ void mma16816(float* c, const uint32_t* a,
                                         uint32_t b0, uint32_t b1) {
    asm volatile(
        "mma.sync.aligned.m16n8k16.row.col.f32.bf16.bf16.f32 "
        "{%0,%1,%2,%3}, {%4,%5,%6,%7}, {%8,%9}, {%0,%1,%2,%3};"
        : "+f"(c[0]), "+f"(c[1]), "+f"(c[2]), "+f"(c[3])
        : "r"(a[0]), "r"(a[1]), "r"(a[2]), "r"(a[3]), "r"(b0), "r"(b1));
}

__device__ __forceinline__ void cpa16(uint32_t dst, const void* src, uint32_t srcsz) {
    asm volatile("cp.async.cg.shared.global [%0], [%1], 16, %2;"
                 :: "r"(dst), "l"(src), "r"(srcsz) : "memory");
}
#define CPA_COMMIT() asm volatile("cp.async.commit_group;" ::: "memory")
#define CPA_WAIT(N)  asm volatile("cp.async.wait_group %0;" :: "n"(N) : "memory")

// Split two fp32 into bf16x2 hi-word + residual bf16x2 lo-word
__device__ __forceinline__ void bsplit2(float x0, float x1, uint32_t& hi, uint32_t& lo) {
    __nv_bfloat16 h0 = __float2bfloat16_rn(x0);
    __nv_bfloat16 h1 = __float2bfloat16_rn(x1);
    float r0 = x0 - __bfloat162float(h0);
    float r1 = x1 - __bfloat162float(h1);
    __nv_bfloat162 hp, lp;
    hp.x = h0; hp.y = h1;
    lp.x = __float2bfloat16_rn(r0); lp.y = __float2bfloat16_rn(r1);
    hi = *reinterpret_cast<uint32_t*>(&hp);
    lo = *reinterpret_cast<uint32_t*>(&lp);
}

// ---------------------------------------------------------------------------
// Conversion kernels: fp32 -> bf16 hi/lo, 8 floats per thread
// ---------------------------------------------------------------------------
__device__ __forceinline__ void conv_body(const float* __restrict__ in,
                                          uint32_t* __restrict__ hi,
                                          uint32_t* __restrict__ lo, int n8)
{
    int idx = blockIdx.x * blockDim.x + threadIdx.x;
    if (idx >= n8) return;
    const float* p = in + (size_t)idx * 8;
    float4 a = *(const float4*)p;
    float4 b = *(const float4*)(p + 4);
    uint32_t h0, l0, h1, l1, h2, l2, h3, l3;
    bsplit2(a.x, a.y, h0, l0);  bsplit2(a.z, a.w, h1, l1);
    bsplit2(b.x, b.y, h2, l2);  bsplit2(b.z, b.w, h3, l3);
    *(uint4*)&hi[(size_t)idx * 4] = make_uint4(h0, h1, h2, h3);
    *(uint4*)&lo[(size_t)idx * 4] = make_uint4(l0, l1, l2, l3);
}

__global__ void k_conv_x(const float* __restrict__ x) {
    conv_body(x, g_xhi, g_xlo, NNODES * K1 / 8);
}
__global__ void k_conv_w1(const float* __restrict__ w) {
    conv_body(w, g_w1hi, g_w1lo, CH * K1 / 8);
}
__global__ void k_conv_w2(const float* __restrict__ w) {
    conv_body(w, g_w2hi, g_w2lo, CH * K2 / 8);
}

// ---------------------------------------------------------------------------
// bf16 split-3 GEMM, cp.async 3-stage pipeline, full-width N=256 tile.
// C[M,256] = A[M,K] @ B[256,K]^T. CTA tile 128x256, BK=32, 512 threads.
// Row layout (128B, SW128): [hi: 32 bf16 = 64B | lo: 32 bf16 = 64B]
// Stage = A(16KB) + B(32KB) = 48KB; 3 stages = 144KB.
// 16 warps: 4m x 4n, warp tile 32x64.
// ---------------------------------------------------------------------------
#define GEMM_NTH   512
#define STAGE_SZ   49152
#define GEMM_SMEM  (3 * STAGE_SZ)

__device__ __forceinline__ void load_chunk(
    const uint32_t* __restrict__ Ahi, const uint32_t* __restrict__ Alo,
    const uint32_t* __restrict__ Bhi, const uint32_t* __restrict__ Blo,
    uint32_t buf, int brow, int M, int K, int k0, int t)
{
    const uint32_t bufA = buf;
    const uint32_t bufB = buf + 16384;
    // A: 128 rows x 8 groups = 1024 items, 2 per thread
#pragma unroll
    for (int it = 0; it < 2; it++) {
        int g = t + it * GEMM_NTH;
        int r = g >> 3, j = g & 7;
        int gr = brow + r;
        const uint32_t* src = (j < 4) ? Ahi : Alo;
        int koff = (j & 3) * 8;
        const void* p = &src[((size_t)gr * K + k0 + koff) >> 1];
        cpa16(bufA + SW128((uint32_t)(r * 128 + j * 16)), p, gr < M ? 16u : 0u);
    }
    // B: 256 rows x 8 groups = 2048 items, 4 per thread
#pragma unroll
    for (int it = 0; it < 4; it++) {
        int g = t + it * GEMM_NTH;
        int r = g >> 3, j = g & 7;
        const uint32_t* src = (j < 4) ? Bhi : Blo;
        int koff = (j & 3) * 8;
        const void* p = &src[((size_t)r * K + k0 + koff) >> 1];
        cpa16(bufB + SW128((uint32_t)(r * 128 + j * 16)), p, 16u);
    }
}

__device__ __forceinline__ void mma_gemm_body(
    const uint32_t* __restrict__ Ahi, const uint32_t* __restrict__ Alo,
    const uint32_t* __restrict__ Bhi, const uint32_t* __restrict__ Blo,
    float* __restrict__ C, int M, int K)
{
    extern __shared__ char dsm_raw[];
    const uint32_t base = smem_u32(dsm_raw);

    const int t    = threadIdx.x;
    const int wid  = t >> 5;
    const int lane = t & 31;
    const int brow = blockIdx.x * 128;

    const int warp_m = (wid >> 2) * 32;   // 0,32,64,96
    const int warp_n = (wid & 3) * 64;    // 0,64,128,192

    float acc[2][8][4];
#pragma unroll
    for (int i = 0; i < 2; i++)
#pragma unroll
        for (int j = 0; j < 8; j++)
#pragma unroll
            for (int q = 0; q < 4; q++) acc[i][j][q] = 0.0f;

    const int lr = lane & 15;
    const int kh = lane >> 4;

    const int nch = K >> 5;

    // prologue: chunks 0,1
    load_chunk(Ahi, Alo, Bhi, Blo, base, brow, M, K, 0, t);
    CPA_COMMIT();
    load_chunk(Ahi, Alo, Bhi, Blo, base + STAGE_SZ, brow, M, K, 32, t);
    CPA_COMMIT();

    for (int c = 0; c < nch; c++) {
        if (c + 2 < nch) {
            uint32_t nxt = base + ((c + 2) % 3) * STAGE_SZ;
            load_chunk(Ahi, Alo, Bhi, Blo, nxt, brow, M, K, (c + 2) << 5, t);
            CPA_COMMIT();
            CPA_WAIT(2);
        } else if (c + 1 < nch) {
            CPA_WAIT(1);
        } else {
            CPA_WAIT(0);
        }
        __syncthreads();

        const uint32_t cur  = base + (c % 3) * STAGE_SZ;
        const uint32_t curA = cur;
        const uint32_t curB = cur + 16384;

#pragma unroll
        for (int s = 0; s < 2; s++) {
            const int jh = s * 2 + kh;     // hi groups 0..3
            const int jl = jh + 4;         // lo groups 4..7

            uint32_t ah[2][4], bh[4][4];
#pragma unroll
            for (int mi = 0; mi < 2; mi++) {
                int r = warp_m + mi * 16 + lr;
                ldsm4(ah[mi], curA + (uint32_t)(r * 128 + ((jh ^ (r & 7)) << 4)));
            }
#pragma unroll
            for (int nj = 0; nj < 4; nj++) {
                int r = warp_n + nj * 16 + lr;
                ldsm4(bh[nj], curB + (uint32_t)(r * 128 + ((jh ^ (r & 7)) << 4)));
            }
            // hi*hi
#pragma unroll
            for (int mi = 0; mi < 2; mi++)
#pragma unroll
                for (int nj = 0; nj < 4; nj++) {
                    mma16816(acc[mi][nj * 2 + 0], ah[mi], bh[nj][0], bh[nj][2]);
                    mma16816(acc[mi][nj * 2 + 1], ah[mi], bh[nj][1], bh[nj][3]);
                }
            // lo*hi
            {
                uint32_t al[2][4];
#pragma unroll
                for (int mi = 0; mi < 2; mi++) {
                    int r = warp_m + mi * 16 + lr;
                    ldsm4(al[mi], curA + (uint32_t)(r * 128 + ((jl ^ (r & 7)) << 4)));
                }
#pragma unroll
                for (int mi = 0; mi < 2; mi++)
#pragma unroll
                    for (int nj = 0; nj < 4; nj++) {
                        mma16816(acc[mi][nj * 2 + 0], al[mi], bh[nj][0], bh[nj][2]);
                        mma16816(acc[mi][nj * 2 + 1], al[mi], bh[nj][1], bh[nj][3]);
                    }
            }
            // hi*lo
            {
                uint32_t bl[4][4];
#pragma unroll
                for (int nj = 0; nj < 4; nj++) {
                    int r = warp_n + nj * 16 + lr;
                    ldsm4(bl[nj], curB + (uint32_t)(r * 128 + ((jl ^ (r & 7)) << 4)));
                }
#pragma unroll
                for (int mi = 0; mi < 2; mi++)
#pragma unroll
                    for (int nj = 0; nj < 4; nj++) {
                        mma16816(acc[mi][nj * 2 + 0], ah[mi], bl[nj][0], bl[nj][2]);
                        mma16816(acc[mi][nj * 2 + 1], ah[mi], bl[nj][1], bl[nj][3]);
                    }
            }
        }
        __syncthreads();
    }

    // epilogue
    const int qr = lane >> 2;
    const int qc = (lane & 3) * 2;
#pragma unroll
    for (int mi = 0; mi < 2; mi++) {
        int r0 = brow + warp_m + mi * 16 + qr;
#pragma unroll
        for (int n8 = 0; n8 < 8; n8++) {
            int col = warp_n + n8 * 8 + qc;
            if (r0 < M) {
                float2 v = make_float2(acc[mi][n8][0], acc[mi][n8][1]);
                *(float2*)&C[(size_t)r0 * 256 + col] = v;
            }
            if (r0 + 8 < M) {
                float2 v = make_float2(acc[mi][n8][2], acc[mi][n8][3]);
                *(float2*)&C[(size_t)(r0 + 8) * 256 + col] = v;
            }
        }
    }
}

__global__ void __launch_bounds__(GEMM_NTH, 1)
k_mmagemm1() { mma_gemm_body(g_xhi, g_xlo, g_w1hi, g_w1lo, g_h1, NNODES, K1); }
__global__ void __launch_bounds__(GEMM_NTH, 1)
k_mmagemm2() { mma_gemm_body(g_hrhi, g_hrlo, g_w2hi, g_w2lo, g_h2, NNODES, K2); }

// ---------------------------------------------------------------------------
// edge_index dtype detection (int64 per spec; tolerate int32)
// ---------------------------------------------------------------------------
__global__ void k_detect(const long long* __restrict__ ei) {
    if (blockIdx.x == 0 && threadIdx.x == 0) {
        int is64 = 1;
        for (int i = 0; i < 256; i++) {
            long long v = ei[i];
            if (v < 0 || v >= NNODES) { is64 = 0; break; }
        }
        g_is64 = is64;
    }
}

__device__ __forceinline__ int edge_idx(const void* ei, int half, int e) {
    if (g_is64) return (int)((const long long*)ei)[(size_t)half * NEDGES + e];
    return ((const int*)ei)[(size_t)half * NEDGES + e];
}

// ---------------------------------------------------------------------------
// CSR build: in-degree -> scan -> bucket fill
// ---------------------------------------------------------------------------
__global__ void k_zero_ideg() {
    int i = blockIdx.x * blockDim.x + threadIdx.x;
    if (i < NNODES) g_ideg[i] = 0;
}

__global__ void k_count(const void* __restrict__ ei) {
    int e = blockIdx.x * blockDim.x + threadIdx.x;
    if (e < NEDGES) atomicAdd(&g_ideg[edge_idx(ei, 1, e)], 1);
}

__global__ void k_dinv() {
    int i = blockIdx.x * blockDim.x + threadIdx.x;
    if (i < NNODES) g_dinv[i] = rsqrtf(1.0f + (float)g_ideg[i]);
}

#define SCAN_T 1024
#define SCAN_C ((NNODES + SCAN_T - 1) / SCAN_T)
__global__ void __launch_bounds__(SCAN_T)
k_scan() {
    __shared__ int part[SCAN_T];
    const int t = threadIdx.x;
    const int start = t * SCAN_C;
    const int end   = min(start + SCAN_C, NNODES);
    int s = 0;
    for (int i = start; i < end; i++) s += g_ideg[i];
    part[t] = s;
    __syncthreads();
    for (int off = 1; off < SCAN_T; off <<= 1) {
        int v = (t >= off) ? part[t - off] : 0;
        __syncthreads();
        part[t] += v;
        __syncthreads();
    }
    int run = part[t] - s;
    for (int i = start; i < end; i++) {
        g_rowptr[i] = run;
        g_cursor[i] = run;
        run += g_ideg[i];
    }
    if (t == SCAN_T - 1) g_rowptr[NNODES] = part[SCAN_T - 1];
}

__global__ void k_fill(const void* __restrict__ ei) {
    int e = blockIdx.x * blockDim.x + threadIdx.x;
    if (e >= NEDGES) return;
    int s = edge_idx(ei, 0, e);
    int d = edge_idx(ei, 1, e);
    int pos = atomicAdd(&g_cursor[d], 1);
    g_esrc[pos] = s;
}

// ---------------------------------------------------------------------------
// Gather aggregation: one warp per node.
// ---------------------------------------------------------------------------
__device__ __forceinline__ void gather_acc(
    const float* __restrict__ h, const float* __restrict__ bias,
    int node, int lane, float4& a0, float4& a1)
{
    const float dv = g_dinv[node];
    const float* hd = h + (size_t)node * CH;
    a0 = *(const float4*)&hd[lane * 4];
    a1 = *(const float4*)&hd[128 + lane * 4];
    const float sv = dv * dv;
    a0.x *= sv; a0.y *= sv; a0.z *= sv; a0.w *= sv;
    a1.x *= sv; a1.y *= sv; a1.z *= sv; a1.w *= sv;

    const int p0 = g_rowptr[node];
    const int p1 = g_rowptr[node + 1];
    for (int p = p0; p < p1; p++) {
        int s = g_esrc[p];
        float w = g_dinv[s] * dv;
        const float* hs = h + (size_t)s * CH;
        float4 v0 = *(const float4*)&hs[lane * 4];
        float4 v1 = *(const float4*)&hs[128 + lane * 4];
        a0.x = fmaf(v0.x, w, a0.x); a0.y = fmaf(v0.y, w, a0.y);
        a0.z = fmaf(v0.z, w, a0.z); a0.w = fmaf(v0.w, w, a0.w);
        a1.x = fmaf(v1.x, w, a1.x); a1.y = fmaf(v1.y, w, a1.y);
        a1.z = fmaf(v1.z, w, a1.z); a1.w = fmaf(v1.w, w, a1.w);
    }

    const float4 b0 = *(const float4*)&bias[lane * 4];
    const float4 b1 = *(const float4*)&bias[128 + lane * 4];
    a0.x += b0.x; a0.y += b0.y; a0.z += b0.z; a0.w += b0.w;
    a1.x += b1.x; a1.y += b1.y; a1.z += b1.z; a1.w += b1.w;
}

// layer 1: relu then emit bf16 hi/lo split directly (GEMM2 input)
__global__ void __launch_bounds__(256)
k_gather1(const float* __restrict__ b1)
{
    const int wid  = threadIdx.x >> 5;
    const int lane = threadIdx.x & 31;
    const int node = blockIdx.x * 8 + wid;
    if (node >= NNODES) return;
    float4 a0, a1;
    gather_acc(g_h1, b1, node, lane, a0, a1);
    a0.x = fmaxf(a0.x, 0.f); a0.y = fmaxf(a0.y, 0.f);
    a0.z = fmaxf(a0.z, 0.f); a0.w = fmaxf(a0.w, 0.f);
    a1.x = fmaxf(a1.x, 0.f); a1.y = fmaxf(a1.y, 0.f);
    a1.z = fmaxf(a1.z, 0.f); a1.w = fmaxf(a1.w, 0.f);

    uint32_t h0, l0, h1, l1;
    size_t bix = (size_t)node * 128 + lane * 2;
    bsplit2(a0.x, a0.y, h0, l0); bsplit2(a0.z, a0.w, h1, l1);
    *(uint2*)&g_hrhi[bix] = make_uint2(h0, h1);
    *(uint2*)&g_hrlo[bix] = make_uint2(l0, l1);
    bsplit2(a1.x, a1.y, h0, l0); bsplit2(a1.z, a1.w, h1, l1);
    *(uint2*)&g_hrhi[bix + 64] = make_uint2(h0, h1);
    *(uint2*)&g_hrlo[bix + 64] = make_uint2(l0, l1);
}

// layer 2: plain output
__global__ void __launch_bounds__(256)
k_gather2(const float* __restrict__ b2, float* __restrict__ out)
{
    const int wid  = threadIdx.x >> 5;
    const int lane = threadIdx.x & 31;
    const int node = blockIdx.x * 8 + wid;
    if (node >= NNODES) return;
    float4 a0, a1;
    gather_acc(g_h2, b2, node, lane, a0, a1);
    float* od = out + (size_t)node * CH;
    *(float4*)&od[lane * 4]       = a0;
    *(float4*)&od[128 + lane * 4] = a1;
}

// ---------------------------------------------------------------------------
// Launch
// ---------------------------------------------------------------------------
extern "C" void kernel_launch(void* const* d_in, const int* in_sizes, int n_in,
                              void* d_out, int out_size)
{
    const float* x   = (const float*)d_in[0];
    const void*  ei  = d_in[1];
    const float* W1  = (const float*)d_in[2];
    const float* b1  = (const float*)d_in[3];
    const float* W2  = (const float*)d_in[4];
    const float* b2  = (const float*)d_in[5];
    float*       out = (float*)d_out;

    static cudaStream_t s2 = nullptr;
    static cudaEvent_t  e0 = nullptr, e1 = nullptr;
    if (!s2) {
        cudaFuncSetAttribute(k_mmagemm1, cudaFuncAttributeMaxDynamicSharedMemorySize, GEMM_SMEM);
        cudaFuncSetAttribute(k_mmagemm2, cudaFuncAttributeMaxDynamicSharedMemorySize, GEMM_SMEM);
        cudaStreamCreateWithFlags(&s2, cudaStreamNonBlocking);
        cudaEventCreateWithFlags(&e0, cudaEventDisableTiming);
        cudaEventCreateWithFlags(&e1, cudaEventDisableTiming);
    }

    const int NTH = 256;
    const int nblk_nodes = (NNODES + NTH - 1) / NTH;
    const int nblk_edges = (NEDGES + NTH - 1) / NTH;
    const int nblk_gather = (NNODES + 7) / 8;

    const int gemm_grid = (NNODES + 127) / 128;   // 391

    // main stream: dtype detection, then fork CSR + weight conversions onto s2
    k_detect<<<1, 32>>>((const long long*)ei);
    cudaEventRecord(e0, 0);
    cudaStreamWaitEvent(s2, e0, 0);

    // s2: CSR + dinv + weight conversions (independent of conv_x / GEMM1 start)
    k_conv_w1<<<(CH * K1 / 8 + NTH - 1) / NTH, NTH, 0, s2>>>(W1);
    k_conv_w2<<<(CH * K2 / 8 + NTH - 1) / NTH, NTH, 0, s2>>>(W2);
    k_zero_ideg<<<nblk_nodes, NTH, 0, s2>>>();
    k_count<<<nblk_edges, NTH, 0, s2>>>(ei);
    k_dinv<<<nblk_nodes, NTH, 0, s2>>>();
    k_scan<<<1, SCAN_T, 0, s2>>>();
    k_fill<<<nblk_edges, NTH, 0, s2>>>(ei);
    cudaEventRecord(e1, s2);

    // main: conv_x overlaps the s2 chain; GEMM1 needs conv_x + conv_w1
    k_conv_x<<<(NNODES * K1 / 8 + NTH - 1) / NTH, NTH>>>(x);
    cudaStreamWaitEvent(0, e1, 0);
    k_mmagemm1<<<gemm_grid, GEMM_NTH, GEMM_SMEM>>>();
    k_gather1<<<nblk_gather, NTH>>>(b1);

    // layer 2
    k_mmagemm2<<<gemm_grid, GEMM_NTH, GEMM_SMEM>>>();
    k_gather2<<<nblk_gather, NTH>>>(b2, out);
}

// round 10
// speedup vs baseline: 3.1486x; 1.2643x over previous
#include <cuda_runtime.h>
#include <cuda_bf16.h>
#include <cstdint>

// Problem constants (fixed by the reference)
#define NNODES 50000
#define NEDGES 400000
#define CH     256
#define K1     512
#define K2     256

// ---------------------------------------------------------------------------
// Scratch (__device__ globals; no allocations)
// ---------------------------------------------------------------------------
__device__ float    g_h1[(size_t)NNODES * CH];      // GEMM1 out
__device__ float    g_h2[(size_t)NNODES * CH];      // GEMM2 out
__device__ float    g_dinv[NNODES];
__device__ int      g_ideg[NNODES];
__device__ int      g_rowptr[NNODES + 1];
__device__ int      g_cursor[NNODES];
__device__ int      g_esrc[NEDGES];
__device__ int      g_is64;

// bf16 hi/lo pre-converted operands (u32 = packed bf16x2)
__device__ uint32_t g_xhi[(size_t)NNODES * K1 / 2];
__device__ uint32_t g_xlo[(size_t)NNODES * K1 / 2];
__device__ uint32_t g_hrhi[(size_t)NNODES * K2 / 2];
__device__ uint32_t g_hrlo[(size_t)NNODES * K2 / 2];
__device__ uint32_t g_w1hi[CH * K1 / 2];
__device__ uint32_t g_w1lo[CH * K1 / 2];
__device__ uint32_t g_w2hi[CH * K2 / 2];
__device__ uint32_t g_w2lo[CH * K2 / 2];

// ---------------------------------------------------------------------------
// Helpers
// ---------------------------------------------------------------------------
__device__ __forceinline__ uint32_t smem_u32(const void* p) {
    uint32_t a;
    asm("{ .reg .u64 t; cvta.to.shared.u64 t, %1; cvt.u32.u64 %0, t; }" : "=r"(a) : "l"(p));
    return a;
}

#define SW128(o) ((o) ^ (((o) >> 3) & 0x70))

__device__ __forceinline__ void ldsm4(uint32_t* r, uint32_t addr) {
    asm volatile("ldmatrix.sync.aligned.m8n8.x4.shared.b16 {%0,%1,%2,%3}, [%4];"
                 : "=r"(r[0]), "=r"(r[1]), "=r"(r[2]), "=r"(r[3]) : "r"(addr));
}

__device__ __forceinline__ void mma16816(float* c, const uint32_t* a,
                                         uint32_t b0, uint32_t b1) {
    asm volatile(
        "mma.sync.aligned.m16n8k16.row.col.f32.bf16.bf16.f32 "
        "{%0,%1,%2,%3}, {%4,%5,%6,%7}, {%8,%9}, {%0,%1,%2,%3};"
        : "+f"(c[0]), "+f"(c[1]), "+f"(c[2]), "+f"(c[3])
        : "r"(a[0]), "r"(a[1]), "r"(a[2]), "r"(a[3]), "r"(b0), "r"(b1));
}

__device__ __forceinline__ void cpa16(uint32_t dst, const void* src, uint32_t srcsz) {
    asm volatile("cp.async.cg.shared.global [%0], [%1], 16, %2;"
                 :: "r"(dst), "l"(src), "r"(srcsz) : "memory");
}
#define CPA_COMMIT() asm volatile("cp.async.commit_group;" ::: "memory")
#define CPA_WAIT(N)  asm volatile("cp.async.wait_group %0;" :: "n"(N) : "memory")

// Split two fp32 into bf16x2 hi-word + residual bf16x2 lo-word
__device__ __forceinline__ void bsplit2(float x0, float x1, uint32_t& hi, uint32_t& lo) {
    __nv_bfloat16 h0 = __float2bfloat16_rn(x0);
    __nv_bfloat16 h1 = __float2bfloat16_rn(x1);
    float r0 = x0 - __bfloat162float(h0);
    float r1 = x1 - __bfloat162float(h1);
    __nv_bfloat162 hp, lp;
    hp.x = h0; hp.y = h1;
    lp.x = __float2bfloat16_rn(r0); lp.y = __float2bfloat16_rn(r1);
    hi = *reinterpret_cast<uint32_t*>(&hp);
    lo = *reinterpret_cast<uint32_t*>(&lp);
}

// ---------------------------------------------------------------------------
// Conversion kernels: fp32 -> bf16 hi/lo, 8 floats per thread
// ---------------------------------------------------------------------------
__device__ __forceinline__ void conv_body(const float* __restrict__ in,
                                          uint32_t* __restrict__ hi,
                                          uint32_t* __restrict__ lo, int n8)
{
    int idx = blockIdx.x * blockDim.x + threadIdx.x;
    if (idx >= n8) return;
    const float* p = in + (size_t)idx * 8;
    float4 a = *(const float4*)p;
    float4 b = *(const float4*)(p + 4);
    uint32_t h0, l0, h1, l1, h2, l2, h3, l3;
    bsplit2(a.x, a.y, h0, l0);  bsplit2(a.z, a.w, h1, l1);
    bsplit2(b.x, b.y, h2, l2);  bsplit2(b.z, b.w, h3, l3);
    *(uint4*)&hi[(size_t)idx * 4] = make_uint4(h0, h1, h2, h3);
    *(uint4*)&lo[(size_t)idx * 4] = make_uint4(l0, l1, l2, l3);
}

__global__ void k_conv_x(const float* __restrict__ x) {
    conv_body(x, g_xhi, g_xlo, NNODES * K1 / 8);
}
__global__ void k_conv_w1(const float* __restrict__ w) {
    conv_body(w, g_w1hi, g_w1lo, CH * K1 / 8);
}
__global__ void k_conv_w2(const float* __restrict__ w) {
    conv_body(w, g_w2hi, g_w2lo, CH * K2 / 8);
}

// ---------------------------------------------------------------------------
// bf16 split-3 GEMM, cp.async 3-stage pipeline, full-width N=256 tile.
// C[M,256] = A[M,K] @ B[256,K]^T. CTA tile 128x256, BK=32, 512 threads.
// Row layout (128B, SW128): [hi: 32 bf16 = 64B | lo: 32 bf16 = 64B]
// Stage = A(16KB) + B(32KB) = 48KB; 3 stages = 144KB.
// 16 warps: 4m x 4n, warp tile 32x64.
// ---------------------------------------------------------------------------
#define GEMM_NTH   512
#define STAGE_SZ   49152
#define GEMM_SMEM  (3 * STAGE_SZ)

__device__ __forceinline__ void load_chunk(
    const uint32_t* __restrict__ Ahi, const uint32_t* __restrict__ Alo,
    const uint32_t* __restrict__ Bhi, const uint32_t* __restrict__ Blo,
    uint32_t buf, int brow, int M, int K, int k0, int t)
{
    const uint32_t bufA = buf;
    const uint32_t bufB = buf + 16384;
    // A: 128 rows x 8 groups = 1024 items, 2 per thread
#pragma unroll
    for (int it = 0; it < 2; it++) {
        int g = t + it * GEMM_NTH;
        int r = g >> 3, j = g & 7;
        int gr = brow + r;
        const uint32_t* src = (j < 4) ? Ahi : Alo;
        int koff = (j & 3) * 8;
        const void* p = &src[((size_t)gr * K + k0 + koff) >> 1];
        cpa16(bufA + SW128((uint32_t)(r * 128 + j * 16)), p, gr < M ? 16u : 0u);
    }
    // B: 256 rows x 8 groups = 2048 items, 4 per thread
#pragma unroll
    for (int it = 0; it < 4; it++) {
        int g = t + it * GEMM_NTH;
        int r = g >> 3, j = g & 7;
        const uint32_t* src = (j < 4) ? Bhi : Blo;
        int koff = (j & 3) * 8;
        const void* p = &src[((size_t)r * K + k0 + koff) >> 1];
        cpa16(bufB + SW128((uint32_t)(r * 128 + j * 16)), p, 16u);
    }
}

__device__ __forceinline__ void mma_gemm_body(
    const uint32_t* __restrict__ Ahi, const uint32_t* __restrict__ Alo,
    const uint32_t* __restrict__ Bhi, const uint32_t* __restrict__ Blo,
    float* __restrict__ C, int M, int K)
{
    extern __shared__ char dsm_raw[];
    const uint32_t base = smem_u32(dsm_raw);

    const int t    = threadIdx.x;
    const int wid  = t >> 5;
    const int lane = t & 31;
    const int brow = blockIdx.x * 128;

    const int warp_m = (wid >> 2) * 32;   // 0,32,64,96
    const int warp_n = (wid & 3) * 64;    // 0,64,128,192

    float acc[2][8][4];
#pragma unroll
    for (int i = 0; i < 2; i++)
#pragma unroll
        for (int j = 0; j < 8; j++)
#pragma unroll
            for (int q = 0; q < 4; q++) acc[i][j][q] = 0.0f;

    const int lr = lane & 15;
    const int kh = lane >> 4;

    const int nch = K >> 5;

    // prologue: chunks 0,1
    load_chunk(Ahi, Alo, Bhi, Blo, base, brow, M, K, 0, t);
    CPA_COMMIT();
    load_chunk(Ahi, Alo, Bhi, Blo, base + STAGE_SZ, brow, M, K, 32, t);
    CPA_COMMIT();

    for (int c = 0; c < nch; c++) {
        if (c + 2 < nch) {
            uint32_t nxt = base + ((c + 2) % 3) * STAGE_SZ;
            load_chunk(Ahi, Alo, Bhi, Blo, nxt, brow, M, K, (c + 2) << 5, t);
            CPA_COMMIT();
            CPA_WAIT(2);
        } else if (c + 1 < nch) {
            CPA_WAIT(1);
        } else {
            CPA_WAIT(0);
        }
        __syncthreads();

        const uint32_t cur  = base + (c % 3) * STAGE_SZ;
        const uint32_t curA = cur;
        const uint32_t curB = cur + 16384;

#pragma unroll
        for (int s = 0; s < 2; s++) {
            const int jh = s * 2 + kh;     // hi groups 0..3
            const int jl = jh + 4;         // lo groups 4..7

            uint32_t ah[2][4], bh[4][4];
#pragma unroll
            for (int mi = 0; mi < 2; mi++) {
                int r = warp_m + mi * 16 + lr;
                ldsm4(ah[mi], curA + (uint32_t)(r * 128 + ((jh ^ (r & 7)) << 4)));
            }
#pragma unroll
            for (int nj = 0; nj < 4; nj++) {
                int r = warp_n + nj * 16 + lr;
                ldsm4(bh[nj], curB + (uint32_t)(r * 128 + ((jh ^ (r & 7)) << 4)));
            }
            // hi*hi
#pragma unroll
            for (int mi = 0; mi < 2; mi++)
#pragma unroll
                for (int nj = 0; nj < 4; nj++) {
                    mma16816(acc[mi][nj * 2 + 0], ah[mi], bh[nj][0], bh[nj][2]);
                    mma16816(acc[mi][nj * 2 + 1], ah[mi], bh[nj][1], bh[nj][3]);
                }
            // lo*hi
            {
                uint32_t al[2][4];
#pragma unroll
                for (int mi = 0; mi < 2; mi++) {
                    int r = warp_m + mi * 16 + lr;
                    ldsm4(al[mi], curA + (uint32_t)(r * 128 + ((jl ^ (r & 7)) << 4)));
                }
#pragma unroll
                for (int mi = 0; mi < 2; mi++)
#pragma unroll
                    for (int nj = 0; nj < 4; nj++) {
                        mma16816(acc[mi][nj * 2 + 0], al[mi], bh[nj][0], bh[nj][2]);
                        mma16816(acc[mi][nj * 2 + 1], al[mi], bh[nj][1], bh[nj][3]);
                    }
            }
            // hi*lo
            {
                uint32_t bl[4][4];
#pragma unroll
                for (int nj = 0; nj < 4; nj++) {
                    int r = warp_n + nj * 16 + lr;
                    ldsm4(bl[nj], curB + (uint32_t)(r * 128 + ((jl ^ (r & 7)) << 4)));
                }
#pragma unroll
                for (int mi = 0; mi < 2; mi++)
#pragma unroll
                    for (int nj = 0; nj < 4; nj++) {
                        mma16816(acc[mi][nj * 2 + 0], ah[mi], bl[nj][0], bl[nj][2]);
                        mma16816(acc[mi][nj * 2 + 1], ah[mi], bl[nj][1], bl[nj][3]);
                    }
            }
        }
        __syncthreads();
    }

    // epilogue
    const int qr = lane >> 2;
    const int qc = (lane & 3) * 2;
#pragma unroll
    for (int mi = 0; mi < 2; mi++) {
        int r0 = brow + warp_m + mi * 16 + qr;
#pragma unroll
        for (int n8 = 0; n8 < 8; n8++) {
            int col = warp_n + n8 * 8 + qc;
            if (r0 < M) {
                float2 v = make_float2(acc[mi][n8][0], acc[mi][n8][1]);
                *(float2*)&C[(size_t)r0 * 256 + col] = v;
            }
            if (r0 + 8 < M) {
                float2 v = make_float2(acc[mi][n8][2], acc[mi][n8][3]);
                *(float2*)&C[(size_t)(r0 + 8) * 256 + col] = v;
            }
        }
    }
}

__global__ void __launch_bounds__(GEMM_NTH, 1)
k_mmagemm1() { mma_gemm_body(g_xhi, g_xlo, g_w1hi, g_w1lo, g_h1, NNODES, K1); }
__global__ void __launch_bounds__(GEMM_NTH, 1)
k_mmagemm2() { mma_gemm_body(g_hrhi, g_hrlo, g_w2hi, g_w2lo, g_h2, NNODES, K2); }

// ---------------------------------------------------------------------------
// edge_index access (int64 per spec; tolerate int32 via runtime detection)
// ---------------------------------------------------------------------------
__device__ __forceinline__ int edge_idx(const void* ei, int half, int e) {
    if (g_is64) return (int)((const long long*)ei)[(size_t)half * NEDGES + e];
    return ((const int*)ei)[(size_t)half * NEDGES + e];
}

// ---------------------------------------------------------------------------
// CSR build: zero+detect -> count -> scan(+dinv) -> fill
// ---------------------------------------------------------------------------
__global__ void k_zero_detect(const long long* __restrict__ ei) {
    int i = blockIdx.x * blockDim.x + threadIdx.x;
    if (i < NNODES) g_ideg[i] = 0;
    if (blockIdx.x == 0 && threadIdx.x == 0) {
        int is64 = 1;
        for (int q = 0; q < 256; q++) {
            long long v = ei[q];
            if (v < 0 || v >= NNODES) { is64 = 0; break; }
        }
        g_is64 = is64;
    }
}

__global__ void k_count(const void* __restrict__ ei) {
    int e = blockIdx.x * blockDim.x + threadIdx.x;
    if (e < NEDGES) atomicAdd(&g_ideg[edge_idx(ei, 1, e)], 1);
}

#define SCAN_T 1024
#define SCAN_C ((NNODES + SCAN_T - 1) / SCAN_T)
__global__ void __launch_bounds__(SCAN_T)
k_scan() {
    __shared__ int part[SCAN_T];
    const int t = threadIdx.x;
    const int start = t * SCAN_C;
    const int end   = min(start + SCAN_C, NNODES);
    int s = 0;
    for (int i = start; i < end; i++) s += g_ideg[i];
    part[t] = s;
    __syncthreads();
    for (int off = 1; off < SCAN_T; off <<= 1) {
        int v = (t >= off) ? part[t - off] : 0;
        __syncthreads();
        part[t] += v;
        __syncthreads();
    }
    int run = part[t] - s;
    for (int i = start; i < end; i++) {
        int d = g_ideg[i];
        g_rowptr[i] = run;
        g_cursor[i] = run;
        g_dinv[i]   = rsqrtf(1.0f + (float)d);
        run += d;
    }
    if (t == SCAN_T - 1) g_rowptr[NNODES] = part[SCAN_T - 1];
}

__global__ void k_fill(const void* __restrict__ ei) {
    int e = blockIdx.x * blockDim.x + threadIdx.x;
    if (e >= NEDGES) return;
    int s = edge_idx(ei, 0, e);
    int d = edge_idx(ei, 1, e);
    int pos = atomicAdd(&g_cursor[d], 1);
    g_esrc[pos] = s;
}

// ---------------------------------------------------------------------------
// Gather aggregation: one warp per node.
// ---------------------------------------------------------------------------
__device__ __forceinline__ void gather_acc(
    const float* __restrict__ h, const float* __restrict__ bias,
    int node, int lane, float4& a0, float4& a1)
{
    const float dv = g_dinv[node];
    const float* hd = h + (size_t)node * CH;
    a0 = *(const float4*)&hd[lane * 4];
    a1 = *(const float4*)&hd[128 + lane * 4];
    const float sv = dv * dv;
    a0.x *= sv; a0.y *= sv; a0.z *= sv; a0.w *= sv;
    a1.x *= sv; a1.y *= sv; a1.z *= sv; a1.w *= sv;

    const int p0 = g_rowptr[node];
    const int p1 = g_rowptr[node + 1];
    for (int p = p0; p < p1; p++) {
        int s = g_esrc[p];
        float w = g_dinv[s] * dv;
        const float* hs = h + (size_t)s * CH;
        float4 v0 = *(const float4*)&hs[lane * 4];
        float4 v1 = *(const float4*)&hs[128 + lane * 4];
        a0.x = fmaf(v0.x, w, a0.x); a0.y = fmaf(v0.y, w, a0.y);
        a0.z = fmaf(v0.z, w, a0.z); a0.w = fmaf(v0.w, w, a0.w);
        a1.x = fmaf(v1.x, w, a1.x); a1.y = fmaf(v1.y, w, a1.y);
        a1.z = fmaf(v1.z, w, a1.z); a1.w = fmaf(v1.w, w, a1.w);
    }

    const float4 b0 = *(const float4*)&bias[lane * 4];
    const float4 b1 = *(const float4*)&bias[128 + lane * 4];
    a0.x += b0.x; a0.y += b0.y; a0.z += b0.z; a0.w += b0.w;
    a1.x += b1.x; a1.y += b1.y; a1.z += b1.z; a1.w += b1.w;
}

// layer 1: relu then emit bf16 hi/lo split directly (GEMM2 input)
__global__ void __launch_bounds__(256)
k_gather1(const float* __restrict__ b1)
{
    const int wid  = threadIdx.x >> 5;
    const int lane = threadIdx.x & 31;
    const int node = blockIdx.x * 8 + wid;
    if (node >= NNODES) return;
    float4 a0, a1;
    gather_acc(g_h1, b1, node, lane, a0, a1);
    a0.x = fmaxf(a0.x, 0.f); a0.y = fmaxf(a0.y, 0.f);
    a0.z = fmaxf(a0.z, 0.f); a0.w = fmaxf(a0.w, 0.f);
    a1.x = fmaxf(a1.x, 0.f); a1.y = fmaxf(a1.y, 0.f);
    a1.z = fmaxf(a1.z, 0.f); a1.w = fmaxf(a1.w, 0.f);

    uint32_t h0, l0, h1, l1;
    size_t bix = (size_t)node * 128 + lane * 2;
    bsplit2(a0.x, a0.y, h0, l0); bsplit2(a0.z, a0.w, h1, l1);
    *(uint2*)&g_hrhi[bix] = make_uint2(h0, h1);
    *(uint2*)&g_hrlo[bix] = make_uint2(l0, l1);
    bsplit2(a1.x, a1.y, h0, l0); bsplit2(a1.z, a1.w, h1, l1);
    *(uint2*)&g_hrhi[bix + 64] = make_uint2(h0, h1);
    *(uint2*)&g_hrlo[bix + 64] = make_uint2(l0, l1);
}

// layer 2: plain output
__global__ void __launch_bounds__(256)
k_gather2(const float* __restrict__ b2, float* __restrict__ out)
{
    const int wid  = threadIdx.x >> 5;
    const int lane = threadIdx.x & 31;
    const int node = blockIdx.x * 8 + wid;
    if (node >= NNODES) return;
    float4 a0, a1;
    gather_acc(g_h2, b2, node, lane, a0, a1);
    float* od = out + (size_t)node * CH;
    *(float4*)&od[lane * 4]       = a0;
    *(float4*)&od[128 + lane * 4] = a1;
}

// ---------------------------------------------------------------------------
// Launch
// ---------------------------------------------------------------------------
extern "C" void kernel_launch(void* const* d_in, const int* in_sizes, int n_in,
                              void* d_out, int out_size)
{
    const float* x   = (const float*)d_in[0];
    const void*  ei  = d_in[1];
    const float* W1  = (const float*)d_in[2];
    const float* b1  = (const float*)d_in[3];
    const float* W2  = (const float*)d_in[4];
    const float* b2  = (const float*)d_in[5];
    float*       out = (float*)d_out;

    static cudaStream_t s2 = nullptr;
    static cudaEvent_t  e0 = nullptr, e1 = nullptr;
    if (!s2) {
        cudaFuncSetAttribute(k_mmagemm1, cudaFuncAttributeMaxDynamicSharedMemorySize, GEMM_SMEM);
        cudaFuncSetAttribute(k_mmagemm2, cudaFuncAttributeMaxDynamicSharedMemorySize, GEMM_SMEM);
        cudaStreamCreateWithFlags(&s2, cudaStreamNonBlocking);
        cudaEventCreateWithFlags(&e0, cudaEventDisableTiming);
        cudaEventCreateWithFlags(&e1, cudaEventDisableTiming);
    }

    const int NTH = 256;
    const int nblk_nodes = (NNODES + NTH - 1) / NTH;
    const int nblk_edges = (NEDGES + NTH - 1) / NTH;
    const int nblk_gather = (NNODES + 7) / 8;

    const int gemm_grid = (NNODES + 127) / 128;   // 391

    // fork: CSR chain on s2 (only gather1 depends on it)
    cudaEventRecord(e0, 0);
    cudaStreamWaitEvent(s2, e0, 0);
    k_zero_detect<<<nblk_nodes, NTH, 0, s2>>>((const long long*)ei);
    k_count<<<nblk_edges, NTH, 0, s2>>>(ei);
    k_scan<<<1, SCAN_T, 0, s2>>>();
    k_fill<<<nblk_edges, NTH, 0, s2>>>(ei);
    cudaEventRecord(e1, s2);

    // main: conversions + GEMM1 (no CSR dependency)
    k_conv_w1<<<(CH * K1 / 8 + NTH - 1) / NTH, NTH>>>(W1);
    k_conv_w2<<<(CH * K2 / 8 + NTH - 1) / NTH, NTH>>>(W2);
    k_conv_x<<<(NNODES * K1 / 8 + NTH - 1) / NTH, NTH>>>(x);
    k_mmagemm1<<<gemm_grid, GEMM_NTH, GEMM_SMEM>>>();

    // join: gather1 needs CSR + dinv
    cudaStreamWaitEvent(0, e1, 0);
    k_gather1<<<nblk_gather, NTH>>>(b1);

    // layer 2
    k_mmagemm2<<<gemm_grid, GEMM_NTH, GEMM_SMEM>>>();
    k_gather2<<<nblk_gather, NTH>>>(b2, out);
}